// round 10
// baseline (speedup 1.0000x reference)
#include <cuda_runtime.h>
#include <cuda_bf16.h>
#include <cstdint>

#define BATCH 2
#define RDIM  64
#define CDIM  2048
#define EDIM  128
#define HEADS 4
#define DHEAD 32
#define NROWS (BATCH*RDIM*CDIM)      // 262144
#define NBR   (BATCH*RDIM)           // 128
#define NCTA  (NROWS/128)            // 2048
#define PART_STRIDE 4224             // 4*32*32 ktv + 128 ksum floats per CTA

#define PITCH 136                     // bf16 elements per row

typedef unsigned int u32;

// Scratch (device globals)
__device__ float g_ksum[(size_t)NBR * HEADS * DHEAD];
__device__ __align__(16) float g_part[(size_t)NCTA * PART_STRIDE];
__device__ __align__(16) __nv_bfloat16 g_G[NBR][2][128 * PITCH];
__device__ __align__(16) __nv_bfloat16 g_wt[3][2][128 * PITCH];

__device__ __forceinline__ float elu1(float x) {
    return x > 0.f ? x + 1.f : expf(x);
}

__device__ __forceinline__ void mma16816(float* d, const u32* a, u32 b0, u32 b1) {
    asm volatile(
        "mma.sync.aligned.m16n8k16.row.col.f32.bf16.bf16.f32 "
        "{%0,%1,%2,%3}, {%4,%5,%6,%7}, {%8,%9}, {%0,%1,%2,%3};"
        : "+f"(d[0]), "+f"(d[1]), "+f"(d[2]), "+f"(d[3])
        : "r"(a[0]), "r"(a[1]), "r"(a[2]), "r"(a[3]), "r"(b0), "r"(b1));
}

__device__ __forceinline__ void ldsm_x4(u32* r, u32 addr) {
    asm volatile("ldmatrix.sync.aligned.m8n8.x4.shared.b16 {%0,%1,%2,%3}, [%4];"
        : "=r"(r[0]), "=r"(r[1]), "=r"(r[2]), "=r"(r[3]) : "r"(addr));
}

__device__ __forceinline__ void ldsm_x4_t(u32* r, u32 addr) {
    asm volatile("ldmatrix.sync.aligned.m8n8.x4.trans.shared.b16 {%0,%1,%2,%3}, [%4];"
        : "=r"(r[0]), "=r"(r[1]), "=r"(r[2]), "=r"(r[3]) : "r"(addr));
}

__device__ __forceinline__ uint32_t smem_u32(const void* p) {
    uint32_t a;
    asm("{ .reg .u64 t; cvta.to.shared.u64 t, %1; cvt.u32.u64 %0, t; }" : "=r"(a) : "l"(p));
    return a;
}

__device__ __forceinline__ u32 pack_bf2(float x, float y) {
    __nv_bfloat162 p = __floats2bfloat162_rn(x, y);
    return *(u32*)&p;
}
__device__ __forceinline__ float bf_lo(u32 u) {
    return __bfloat162float(*(__nv_bfloat16*)&u);
}
__device__ __forceinline__ float bf_hi(u32 u) {
    return __bfloat162float(((__nv_bfloat16*)&u)[1]);
}

// ---------------------------------------------------------------------------
// 3-pass split GEMM, pass-major MMA order (8 independent accs between deps).
// ---------------------------------------------------------------------------
__device__ __forceinline__ void gemm3p_ldsm(
    u32 aHi, u32 aLo, u32 bHi, u32 bLo, float acc[8][4])
{
#pragma unroll
    for (int k0 = 0; k0 < 128; k0 += 16) {
        const u32 koff = (u32)(k0 * 2);
        u32 ah[4], al[4], bh[4][4], bl[4][4];
        ldsm_x4(ah, aHi + koff);
        ldsm_x4(al, aLo + koff);
#pragma unroll
        for (int np = 0; np < 4; ++np) {
            const u32 boff = koff + (u32)(np * 16 * PITCH * 2);
            ldsm_x4(bh[np], bHi + boff);
            ldsm_x4(bl[np], bLo + boff);
        }
        // pass 1: Ah*Bh (8 independent accumulators)
#pragma unroll
        for (int np = 0; np < 4; ++np) {
            mma16816(acc[2 * np],     ah, bh[np][0], bh[np][1]);
            mma16816(acc[2 * np + 1], ah, bh[np][2], bh[np][3]);
        }
        // pass 2: Ah*Bl
#pragma unroll
        for (int np = 0; np < 4; ++np) {
            mma16816(acc[2 * np],     ah, bl[np][0], bl[np][1]);
            mma16816(acc[2 * np + 1], ah, bl[np][2], bl[np][3]);
        }
        // pass 3: Al*Bh
#pragma unroll
        for (int np = 0; np < 4; ++np) {
            mma16816(acc[2 * np],     al, bh[np][0], bh[np][1]);
            mma16816(acc[2 * np + 1], al, bh[np][2], bh[np][3]);
        }
    }
}

__device__ __forceinline__ u32 a_base(u32 sb, int region, int arow, int lane) {
    return sb + (u32)region +
        (u32)(((arow + (lane & 15)) * PITCH + ((lane & 16) ? 8 : 0)) * 2);
}
__device__ __forceinline__ u32 b_base(u32 sb, int region, int ncol0, int lane) {
    return sb + (u32)region +
        (u32)(((ncol0 + (lane & 7) + ((lane & 16) ? 8 : 0)) * PITCH +
               ((lane & 8) ? 8 : 0)) * 2);
}

// ---------------------------------------------------------------------------
// wprep: W[k][n] fp32 -> Wt[n][k] bf16 hi/lo. grid=3 (Wq, Wk, Wv).
// ---------------------------------------------------------------------------
__global__ __launch_bounds__(256) void wprep_kernel(
    const float* __restrict__ Wq, const float* __restrict__ Wk,
    const float* __restrict__ Wv)
{
    const float* Wl[3] = {Wq, Wk, Wv};
    const float* W = Wl[blockIdx.x];
    __nv_bfloat16* hi = g_wt[blockIdx.x][0];
    __nv_bfloat16* lo = g_wt[blockIdx.x][1];
    for (int i = threadIdx.x; i < 128 * 128; i += 256) {
        int k = i >> 7, n = i & 127;
        float v = W[i];
        __nv_bfloat16 h = __float2bfloat16(v);
        __nv_bfloat16 l = __float2bfloat16(v - __bfloat162float(h));
        hi[n * PITCH + k] = h;
        lo[n * PITCH + k] = l;
    }
}

// ---------------------------------------------------------------------------
// KV + fused per-CTA KtV partial. 128-row tiles, 512 threads.
// ---------------------------------------------------------------------------
#define QA_HI 0
#define QA_LO 34816
#define QB_HI 69632
#define QB_LO 104448
#define KS_HI 139264
#define KS_LO 174080
#define QBIAS 208896
#define QKSUM 210432            // float[8][128]
#define SMEM_KV (QKSUM + 8 * 128 * 4)

__global__ __launch_bounds__(512, 1) void kv_kernel(
    const float* __restrict__ x,
    const float* __restrict__ bk, const float* __restrict__ bv)
{
    extern __shared__ char smem[];
    const u32 sb = smem_u32(smem);
    const int tid = threadIdx.x;
    const int wid = tid >> 5;
    const int lane = tid & 31;
    const int g = lane >> 2, c = lane & 3;
    const size_t row0 = (size_t)blockIdx.x * 128;

    float* sbias = (float*)(smem + QBIAS);
    float* sksum = (float*)(smem + QKSUM);
    if (tid < 128) {
        sbias[tid]       = bk[tid];
        sbias[128 + tid] = bv[tid];
    }

    // load x tile, split hi/lo bf16 into [row][k] layout
    {
        const float4* xg = reinterpret_cast<const float4*>(x + row0 * EDIM);
#pragma unroll
        for (int i = 0; i < 8; ++i) {
            int idx = tid + i * 512;
            int row = idx >> 5;
            int c4  = (idx & 31) << 2;
            float4 v = xg[idx];
            u32 h01 = pack_bf2(v.x, v.y);
            u32 h23 = pack_bf2(v.z, v.w);
            u32 l01 = pack_bf2(v.x - bf_lo(h01), v.y - bf_hi(h01));
            u32 l23 = pack_bf2(v.z - bf_lo(h23), v.w - bf_hi(h23));
            int off = (row * PITCH + c4) * 2;
            *(uint2*)(smem + QA_HI + off) = make_uint2(h01, h23);
            *(uint2*)(smem + QA_LO + off) = make_uint2(l01, l23);
        }
    }

    const int arow = (wid & 7) * 16;
    const int ncol0 = (wid >> 3) * 64;
    const int aw = wid & 7;

    const u32 aHi = a_base(sb, QA_HI, arow, lane);
    const u32 aLo = a_base(sb, QA_LO, arow, lane);
    const u32 bHi = b_base(sb, QB_HI, ncol0, lane);
    const u32 bLo = b_base(sb, QB_LO, ncol0, lane);

    for (int w = 1; w < 3; ++w) {
        __syncthreads();
        {
            const uint4* gh = (const uint4*)g_wt[w][0];
            const uint4* gl = (const uint4*)g_wt[w][1];
            uint4* sh = (uint4*)(smem + QB_HI);
            uint4* sl = (uint4*)(smem + QB_LO);
#pragma unroll
            for (int i = 0; i < 5; ++i) {
                int idx = tid + i * 512;
                if (idx < 2176) { sh[idx] = gh[idx]; sl[idx] = gl[idx]; }
            }
        }
        __syncthreads();

        float acc[8][4];
#pragma unroll
        for (int i = 0; i < 8; ++i)
#pragma unroll
            for (int j = 0; j < 4; ++j) acc[i][j] = 0.f;

        gemm3p_ldsm(aHi, aLo, bHi, bLo, acc);

        if (w == 1) {
            const float* bias = sbias;
#pragma unroll
            for (int nt = 0; nt < 8; ++nt) {
                int col = ncol0 + nt * 8 + 2 * c;
                float2 bb = *(const float2*)(bias + col);
                float k0x = elu1(acc[nt][0] + bb.x), k0y = elu1(acc[nt][1] + bb.y);
                float k1x = elu1(acc[nt][2] + bb.x), k1y = elu1(acc[nt][3] + bb.y);
                u32 h0 = pack_bf2(k0x, k0y);
                u32 h1 = pack_bf2(k1x, k1y);
                u32 l0 = pack_bf2(k0x - bf_lo(h0), k0y - bf_hi(h0));
                u32 l1 = pack_bf2(k1x - bf_lo(h1), k1y - bf_hi(h1));
                int o0 = ((arow + g) * PITCH + col) * 2;
                int o1 = ((arow + g + 8) * PITCH + col) * 2;
                *(u32*)(smem + KS_HI + o0) = h0;
                *(u32*)(smem + KS_LO + o0) = l0;
                *(u32*)(smem + KS_HI + o1) = h1;
                *(u32*)(smem + KS_LO + o1) = l1;
                float s0 = k0x + k1x;
                float s1 = k0y + k1y;
                s0 += __shfl_xor_sync(0xffffffffu, s0, 16);
                s0 += __shfl_xor_sync(0xffffffffu, s0, 8);
                s0 += __shfl_xor_sync(0xffffffffu, s0, 4);
                s1 += __shfl_xor_sync(0xffffffffu, s1, 16);
                s1 += __shfl_xor_sync(0xffffffffu, s1, 8);
                s1 += __shfl_xor_sync(0xffffffffu, s1, 4);
                if (lane < 4) {
                    sksum[aw * 128 + col]     = s0;
                    sksum[aw * 128 + col + 1] = s1;
                }
            }
        } else {
            const float* bias = sbias + 128;
#pragma unroll
            for (int nt = 0; nt < 8; ++nt) {
                int col = ncol0 + nt * 8 + 2 * c;
                float2 bb = *(const float2*)(bias + col);
                acc[nt][0] += bb.x; acc[nt][1] += bb.y;
                acc[nt][2] += bb.x; acc[nt][3] += bb.y;
            }
            __syncthreads();   // everyone done reading QB (Wv)
#pragma unroll
            for (int nt = 0; nt < 8; ++nt) {
                int col = ncol0 + nt * 8 + 2 * c;
                u32 h0 = pack_bf2(acc[nt][0], acc[nt][1]);
                u32 h1 = pack_bf2(acc[nt][2], acc[nt][3]);
                u32 l0 = pack_bf2(acc[nt][0] - bf_lo(h0), acc[nt][1] - bf_hi(h0));
                u32 l1 = pack_bf2(acc[nt][2] - bf_lo(h1), acc[nt][3] - bf_hi(h1));
                int o0 = ((arow + g) * PITCH + col) * 2;
                int o1 = ((arow + g + 8) * PITCH + col) * 2;
                *(u32*)(smem + QB_HI + o0) = h0;
                *(u32*)(smem + QB_LO + o0) = l0;
                *(u32*)(smem + QB_HI + o1) = h1;
                *(u32*)(smem + QB_LO + o1) = l1;
            }
        }
    }

    __syncthreads();   // v-split writes + sksum complete

    if (tid < 128) {
        float s = 0.f;
#pragma unroll
        for (int i = 0; i < 8; ++i) s += sksum[i * 128 + tid];
        g_part[(size_t)blockIdx.x * PART_STRIDE + 4096 + tid] = s;
    }

    // ---- KtV partial phase (pass-major order) ----
    {
        const int h  = wid & 3;
        const int mt = (wid >> 2) & 1;
        const int np = wid >> 3;
        const int d0 = h * 32 + mt * 16;
        const int e0 = h * 32 + np * 16;

        const u32 a_roff = (u32)(((lane & 7) + ((lane & 16) ? 8 : 0)) * (PITCH * 2));
        const u32 a_coff = (u32)((d0 + ((lane & 8) ? 8 : 0)) * 2);
        const u32 b_roff = (u32)(((lane & 7) + ((lane & 8) ? 8 : 0)) * (PITCH * 2));
        const u32 b_coff = (u32)((e0 + ((lane & 16) ? 8 : 0)) * 2);
        const u32 a_hi = sb + KS_HI + a_roff + a_coff;
        const u32 a_lo = sb + KS_LO + a_roff + a_coff;
        const u32 b_hi = sb + QB_HI + b_roff + b_coff;
        const u32 b_lo = sb + QB_LO + b_roff + b_coff;

        float acc[2][4];
#pragma unroll
        for (int i = 0; i < 2; ++i)
#pragma unroll
            for (int j = 0; j < 4; ++j) acc[i][j] = 0.f;

#pragma unroll
        for (int c0 = 0; c0 < 128; c0 += 16) {
            u32 off = (u32)(c0 * (PITCH * 2));
            u32 ah[4], al[4], bh[4], bl[4];
            ldsm_x4_t(ah, a_hi + off);
            ldsm_x4_t(al, a_lo + off);
            ldsm_x4_t(bh, b_hi + off);
            ldsm_x4_t(bl, b_lo + off);
            mma16816(acc[0], ah, bh[0], bh[1]);
            mma16816(acc[1], ah, bh[2], bh[3]);
            mma16816(acc[0], ah, bl[0], bl[1]);
            mma16816(acc[1], ah, bl[2], bl[3]);
            mma16816(acc[0], al, bh[0], bh[1]);
            mma16816(acc[1], al, bh[2], bh[3]);
        }

        float* dst = g_part + (size_t)blockIdx.x * PART_STRIDE + h * 1024;
#pragma unroll
        for (int nt = 0; nt < 2; ++nt) {
            int d_lo = mt * 16 + g;
            int e_lo = np * 16 + nt * 8 + 2 * c;
            *(float2*)&dst[d_lo * 32 + e_lo]       = make_float2(acc[nt][0], acc[nt][1]);
            *(float2*)&dst[(d_lo + 8) * 32 + e_lo] = make_float2(acc[nt][2], acc[nt][3]);
        }
    }
}

// ---------------------------------------------------------------------------
// fold: per (br,h): reduce 16 CTA partials -> KtV; ksum (h==0);
//       G[d][n] = sum_d' KtV[d][d']*Wo[h*32+d'][n] -> split bf16 [n][k].
// ---------------------------------------------------------------------------
__global__ __launch_bounds__(256) void fold_kernel(const float* __restrict__ Wo)
{
    __shared__ float ktv_s[1024];   // [e][d]
    __shared__ float ws[4096];      // Wo slice [32][128]

    const int tid = threadIdx.x;
    const int br  = blockIdx.x >> 2;
    const int h   = blockIdx.x & 3;
    const float* base = g_part + (size_t)br * 16 * PART_STRIDE;

    {
        float v0 = 0.f, v1 = 0.f, v2 = 0.f, v3 = 0.f;
#pragma unroll 4
        for (int i = 0; i < 16; ++i) {
            float4 p = *(const float4*)(base + (size_t)i * PART_STRIDE + h * 1024 + tid * 4);
            v0 += p.x; v1 += p.y; v2 += p.z; v3 += p.w;
        }
        int d = tid >> 3, e0 = (tid & 7) * 4;
        ktv_s[(e0 + 0) * 32 + d] = v0;
        ktv_s[(e0 + 1) * 32 + d] = v1;
        ktv_s[(e0 + 2) * 32 + d] = v2;
        ktv_s[(e0 + 3) * 32 + d] = v3;
    }

    if (h == 0 && tid < 128) {
        float s = 0.f;
#pragma unroll 4
        for (int i = 0; i < 16; ++i)
            s += base[(size_t)i * PART_STRIDE + 4096 + tid];
        g_ksum[(size_t)br * 128 + tid] = s;
    }

    {
        const float4* wg = reinterpret_cast<const float4*>(Wo + h * 4096);
#pragma unroll
        for (int i = 0; i < 4; ++i)
            reinterpret_cast<float4*>(ws)[tid + i * 256] = wg[tid + i * 256];
    }
    __syncthreads();

    {
        const int n  = tid >> 1;
        const int d0 = (tid & 1) * 16;
        float acc[16];
#pragma unroll
        for (int j = 0; j < 16; ++j) acc[j] = 0.f;
#pragma unroll 4
        for (int dp = 0; dp < 32; ++dp) {
            float w = ws[dp * 128 + n];
            const float4* kp = (const float4*)(ktv_s + dp * 32 + d0);
            float4 k0 = kp[0], k1 = kp[1], k2 = kp[2], k3 = kp[3];
            acc[0]  += w * k0.x; acc[1]  += w * k0.y; acc[2]  += w * k0.z; acc[3]  += w * k0.w;
            acc[4]  += w * k1.x; acc[5]  += w * k1.y; acc[6]  += w * k1.z; acc[7]  += w * k1.w;
            acc[8]  += w * k2.x; acc[9]  += w * k2.y; acc[10] += w * k2.z; acc[11] += w * k2.w;
            acc[12] += w * k3.x; acc[13] += w * k3.y; acc[14] += w * k3.z; acc[15] += w * k3.w;
        }
        __nv_bfloat16 hbuf[16], lbuf[16];
#pragma unroll
        for (int j = 0; j < 16; ++j) {
            __nv_bfloat16 hv = __float2bfloat16(acc[j]);
            hbuf[j] = hv;
            lbuf[j] = __float2bfloat16(acc[j] - __bfloat162float(hv));
        }
        int eo = n * PITCH + h * 32 + d0;
        uint4* dh = (uint4*)&g_G[br][0][eo];
        uint4* dl = (uint4*)&g_G[br][1][eo];
        dh[0] = ((uint4*)hbuf)[0]; dh[1] = ((uint4*)hbuf)[1];
        dl[0] = ((uint4*)lbuf)[0]; dl[1] = ((uint4*)lbuf)[1];
    }
}

// ---------------------------------------------------------------------------
// out: q = elu(x@Wq+bq); z = 1/(q.ksum+eps);
//      out = sum_h z_h * (q_h @ G_h) + bo.  128-row tiles, 512 threads.
// ---------------------------------------------------------------------------
#define OA_HI 0
#define OA_LO 34816
#define OB_HI 69632
#define OB_LO 104448
#define OKS   139264            // ksum 128f
#define OZ    139776            // z 512f
#define OBQ   141824            // bq 128f
#define OBO   142336            // bo 128f
#define SMEM_OUT (OBO + 512)

__global__ __launch_bounds__(512, 1) void out_kernel(
    const float* __restrict__ x, const float* __restrict__ bq,
    const float* __restrict__ bo, float* __restrict__ out)
{
    extern __shared__ char smem[];
    const u32 sb = smem_u32(smem);
    const int tid = threadIdx.x;
    const int wid = tid >> 5;
    const int lane = tid & 31;
    const int g = lane >> 2, c = lane & 3;
    const size_t row0 = (size_t)blockIdx.x * 128;
    const int br = blockIdx.x >> 4;

    float* ks_s = (float*)(smem + OKS);
    float* zs   = (float*)(smem + OZ);
    float* bq_s = (float*)(smem + OBQ);
    float* bo_s = (float*)(smem + OBO);

    if (tid < 128) ks_s[tid] = g_ksum[(size_t)br * 128 + tid];
    else if (tid < 256) bq_s[tid - 128] = bq[tid - 128];
    else if (tid < 384) bo_s[tid - 256] = bo[tid - 256];

    // load x tile split into OA; Wq split into OB
    {
        const float4* xg = reinterpret_cast<const float4*>(x + row0 * EDIM);
#pragma unroll
        for (int i = 0; i < 8; ++i) {
            int idx = tid + i * 512;
            int row = idx >> 5;
            int c4  = (idx & 31) << 2;
            float4 v = xg[idx];
            u32 h01 = pack_bf2(v.x, v.y);
            u32 h23 = pack_bf2(v.z, v.w);
            u32 l01 = pack_bf2(v.x - bf_lo(h01), v.y - bf_hi(h01));
            u32 l23 = pack_bf2(v.z - bf_lo(h23), v.w - bf_hi(h23));
            int off = (row * PITCH + c4) * 2;
            *(uint2*)(smem + OA_HI + off) = make_uint2(h01, h23);
            *(uint2*)(smem + OA_LO + off) = make_uint2(l01, l23);
        }
        const uint4* gh = (const uint4*)g_wt[0][0];
        const uint4* gl = (const uint4*)g_wt[0][1];
        uint4* sh = (uint4*)(smem + OB_HI);
        uint4* sl = (uint4*)(smem + OB_LO);
#pragma unroll
        for (int i = 0; i < 5; ++i) {
            int idx = tid + i * 512;
            if (idx < 2176) { sh[idx] = gh[idx]; sl[idx] = gl[idx]; }
        }
    }
    __syncthreads();

    const int arow = (wid & 7) * 16;
    const int ncol0 = (wid >> 3) * 64;
    const u32 aHi = a_base(sb, OA_HI, arow, lane);
    const u32 aLo = a_base(sb, OA_LO, arow, lane);
    const u32 bHi = b_base(sb, OB_HI, ncol0, lane);
    const u32 bLo = b_base(sb, OB_LO, ncol0, lane);

    // q = x @ Wq (3-pass)
    float qa[8][4];
#pragma unroll
    for (int i = 0; i < 8; ++i)
#pragma unroll
        for (int j = 0; j < 4; ++j) qa[i][j] = 0.f;
    gemm3p_ldsm(aHi, aLo, bHi, bLo, qa);

    __syncthreads();   // all x reads (OA) + Wq reads (OB) done

    // bias + elu, split q fragments into OA
#pragma unroll
    for (int nt = 0; nt < 8; ++nt) {
        int col = ncol0 + nt * 8 + 2 * c;
        float2 bb = *(const float2*)(bq_s + col);
        float q0x = elu1(qa[nt][0] + bb.x), q0y = elu1(qa[nt][1] + bb.y);
        float q1x = elu1(qa[nt][2] + bb.x), q1y = elu1(qa[nt][3] + bb.y);
        u32 h0 = pack_bf2(q0x, q0y);
        u32 h1 = pack_bf2(q1x, q1y);
        u32 l0 = pack_bf2(q0x - bf_lo(h0), q0y - bf_hi(h0));
        u32 l1 = pack_bf2(q1x - bf_lo(h1), q1y - bf_hi(h1));
        int o0 = ((arow + g) * PITCH + col) * 2;
        int o1 = ((arow + g + 8) * PITCH + col) * 2;
        *(u32*)(smem + OA_HI + o0) = h0;
        *(u32*)(smem + OA_LO + o0) = l0;
        *(u32*)(smem + OA_HI + o1) = h1;
        *(u32*)(smem + OA_LO + o1) = l1;
    }

    // load G into OB (Wq dead)
    {
        const uint4* gh = (const uint4*)g_G[br][0];
        const uint4* gl = (const uint4*)g_G[br][1];
        uint4* sh = (uint4*)(smem + OB_HI);
        uint4* sl = (uint4*)(smem + OB_LO);
#pragma unroll
        for (int i = 0; i < 5; ++i) {
            int idx = tid + i * 512;
            if (idx < 2176) { sh[idx] = gh[idx]; sl[idx] = gl[idx]; }
        }
    }
    __syncthreads();   // q split + G ready

    // z per (row, head)
    {
        const int row = tid >> 2;
        const int h   = tid & 3;
        const u32 bh0 = (u32)((row * PITCH + h * 32) * 2);
        const float* ksp = ks_s + h * 32;
        float dot = 0.f;
#pragma unroll
        for (int i = 0; i < 16; ++i) {
            u32 uh = *(const u32*)(smem + OA_HI + bh0 + i * 4);
            u32 ul = *(const u32*)(smem + OA_LO + bh0 + i * 4);
            dot += (bf_lo(uh) + bf_lo(ul)) * ksp[2 * i];
            dot += (bf_hi(uh) + bf_hi(ul)) * ksp[2 * i + 1];
        }
        zs[row * 4 + h] = 1.f / (dot + 1e-6f);
    }
    __syncthreads();

    // out = sum_h z_h * (q_h @ G_h) + bo  (pass-major MMA order per head)
    {
        float acc[8][4];
#pragma unroll
        for (int i = 0; i < 8; ++i)
#pragma unroll
            for (int j = 0; j < 4; ++j) acc[i][j] = 0.f;

#pragma unroll
        for (int h = 0; h < 4; ++h) {
            float pacc[8][4];
#pragma unroll
            for (int i = 0; i < 8; ++i)
#pragma unroll
                for (int j = 0; j < 4; ++j) pacc[i][j] = 0.f;

#pragma unroll
            for (int ks = 0; ks < 2; ++ks) {
                const u32 koff = (u32)((h * 32 + ks * 16) * 2);
                u32 ah[4], al[4], bh[4][4], bl[4][4];
                ldsm_x4(ah, aHi + koff);
                ldsm_x4(al, aLo + koff);
#pragma unroll
                for (int np = 0; np < 4; ++np) {
                    const u32 boff = koff + (u32)(np * 16 * PITCH * 2);
                    ldsm_x4(bh[np], bHi + boff);
                    ldsm_x4(bl[np], bLo + boff);
                }
#pragma unroll
                for (int np = 0; np < 4; ++np) {
                    mma16816(pacc[2 * np],     ah, bh[np][0], bh[np][1]);
                    mma16816(pacc[2 * np + 1], ah, bh[np][2], bh[np][3]);
                }
#pragma unroll
                for (int np = 0; np < 4; ++np) {
                    mma16816(pacc[2 * np],     ah, bl[np][0], bl[np][1]);
                    mma16816(pacc[2 * np + 1], ah, bl[np][2], bl[np][3]);
                }
#pragma unroll
                for (int np = 0; np < 4; ++np) {
                    mma16816(pacc[2 * np],     al, bh[np][0], bh[np][1]);
                    mma16816(pacc[2 * np + 1], al, bh[np][2], bh[np][3]);
                }
            }
            float z0 = zs[(arow + g) * 4 + h];
            float z1 = zs[(arow + g + 8) * 4 + h];
#pragma unroll
            for (int nt = 0; nt < 8; ++nt) {
                acc[nt][0] += z0 * pacc[nt][0];
                acc[nt][1] += z0 * pacc[nt][1];
                acc[nt][2] += z1 * pacc[nt][2];
                acc[nt][3] += z1 * pacc[nt][3];
            }
        }

#pragma unroll
        for (int nt = 0; nt < 8; ++nt) {
            int col = ncol0 + nt * 8 + 2 * c;
            float2 bb = *(const float2*)(bo_s + col);
            float2 r0, r1;
            r0.x = acc[nt][0] + bb.x; r0.y = acc[nt][1] + bb.y;
            r1.x = acc[nt][2] + bb.x; r1.y = acc[nt][3] + bb.y;
            size_t ra = row0 + arow + g;
            *(float2*)(out + ra * EDIM + col)       = r0;
            *(float2*)(out + (ra + 8) * EDIM + col) = r1;
        }
    }
}

// ---------------------------------------------------------------------------
extern "C" void kernel_launch(void* const* d_in, const int* in_sizes, int n_in,
                              void* d_out, int out_size)
{
    const float* x  = (const float*)d_in[0];
    const float* Wq = (const float*)d_in[1];
    const float* bq = (const float*)d_in[2];
    const float* Wk = (const float*)d_in[3];
    const float* bk = (const float*)d_in[4];
    const float* Wv = (const float*)d_in[5];
    const float* bv = (const float*)d_in[6];
    const float* Wo = (const float*)d_in[7];
    const float* bo = (const float*)d_in[8];
    float* out = (float*)d_out;

    cudaFuncSetAttribute(kv_kernel, cudaFuncAttributeMaxDynamicSharedMemorySize, SMEM_KV);
    cudaFuncSetAttribute(out_kernel, cudaFuncAttributeMaxDynamicSharedMemorySize, SMEM_OUT);

    wprep_kernel<<<3, 256>>>(Wq, Wk, Wv);
    kv_kernel<<<NCTA, 512, SMEM_KV>>>(x, bk, bv);
    fold_kernel<<<NBR * HEADS, 256>>>(Wo);
    out_kernel<<<NCTA, 512, SMEM_OUT>>>(x, bq, bo, out);
}

// round 11
// speedup vs baseline: 1.0776x; 1.0776x over previous
#include <cuda_runtime.h>
#include <cuda_bf16.h>
#include <cstdint>

#define BATCH 2
#define RDIM  64
#define CDIM  2048
#define EDIM  128
#define HEADS 4
#define DHEAD 32
#define NROWS (BATCH*RDIM*CDIM)      // 262144
#define NBR   (BATCH*RDIM)           // 128
#define NCTA  (NROWS/128)            // 2048
#define PART_STRIDE 4224

#define PITCH 136                     // bf16 elements per row

typedef unsigned int u32;

// Scratch (device globals)
__device__ float g_ksum[(size_t)NBR * HEADS * DHEAD];
__device__ __align__(16) float g_part[(size_t)NCTA * PART_STRIDE];
__device__ __align__(16) __nv_bfloat16 g_G[NBR][2][128 * PITCH];
__device__ __align__(16) __nv_bfloat16 g_wt[3][2][128 * PITCH];

__device__ __forceinline__ float elu1(float x) {
    return x > 0.f ? x + 1.f : expf(x);
}

__device__ __forceinline__ void mma16816(float* d, const u32* a, u32 b0, u32 b1) {
    asm volatile(
        "mma.sync.aligned.m16n8k16.row.col.f32.bf16.bf16.f32 "
        "{%0,%1,%2,%3}, {%4,%5,%6,%7}, {%8,%9}, {%0,%1,%2,%3};"
        : "+f"(d[0]), "+f"(d[1]), "+f"(d[2]), "+f"(d[3])
        : "r"(a[0]), "r"(a[1]), "r"(a[2]), "r"(a[3]), "r"(b0), "r"(b1));
}

__device__ __forceinline__ void ldsm_x4(u32* r, u32 addr) {
    asm volatile("ldmatrix.sync.aligned.m8n8.x4.shared.b16 {%0,%1,%2,%3}, [%4];"
        : "=r"(r[0]), "=r"(r[1]), "=r"(r[2]), "=r"(r[3]) : "r"(addr));
}

__device__ __forceinline__ void ldsm_x4_t(u32* r, u32 addr) {
    asm volatile("ldmatrix.sync.aligned.m8n8.x4.trans.shared.b16 {%0,%1,%2,%3}, [%4];"
        : "=r"(r[0]), "=r"(r[1]), "=r"(r[2]), "=r"(r[3]) : "r"(addr));
}

__device__ __forceinline__ uint32_t smem_u32(const void* p) {
    uint32_t a;
    asm("{ .reg .u64 t; cvta.to.shared.u64 t, %1; cvt.u32.u64 %0, t; }" : "=r"(a) : "l"(p));
    return a;
}

__device__ __forceinline__ void cp_async16(u32 saddr, const void* gptr) {
    asm volatile("cp.async.cg.shared.global [%0], [%1], 16;"
        :: "r"(saddr), "l"(gptr));
}
#define CP_COMMIT() asm volatile("cp.async.commit_group;" ::: "memory")
#define CP_WAIT0()  asm volatile("cp.async.wait_group 0;" ::: "memory")

__device__ __forceinline__ u32 pack_bf2(float x, float y) {
    __nv_bfloat162 p = __floats2bfloat162_rn(x, y);
    return *(u32*)&p;
}
__device__ __forceinline__ float bf_lo(u32 u) {
    return __bfloat162float(*(__nv_bfloat16*)&u);
}
__device__ __forceinline__ float bf_hi(u32 u) {
    return __bfloat162float(((__nv_bfloat16*)&u)[1]);
}

// 3-pass split GEMM (R9 acc-major order — proven fastest).
__device__ __forceinline__ void gemm3p_ldsm(
    u32 aHi, u32 aLo, u32 bHi, u32 bLo, float acc[8][4])
{
#pragma unroll
    for (int k0 = 0; k0 < 128; k0 += 16) {
        const u32 koff = (u32)(k0 * 2);
        u32 ah[4], al[4];
        ldsm_x4(ah, aHi + koff);
        ldsm_x4(al, aLo + koff);
#pragma unroll
        for (int np = 0; np < 4; ++np) {
            const u32 boff = koff + (u32)(np * 16 * PITCH * 2);
            u32 bh[4], bl[4];
            ldsm_x4(bh, bHi + boff);
            ldsm_x4(bl, bLo + boff);
            mma16816(acc[2 * np],     ah, bh[0], bh[1]);
            mma16816(acc[2 * np],     ah, bl[0], bl[1]);
            mma16816(acc[2 * np],     al, bh[0], bh[1]);
            mma16816(acc[2 * np + 1], ah, bh[2], bh[3]);
            mma16816(acc[2 * np + 1], ah, bl[2], bl[3]);
            mma16816(acc[2 * np + 1], al, bh[2], bh[3]);
        }
    }
}

__device__ __forceinline__ u32 a_base(u32 sb, int region, int arow, int lane) {
    return sb + (u32)region +
        (u32)(((arow + (lane & 15)) * PITCH + ((lane & 16) ? 8 : 0)) * 2);
}
__device__ __forceinline__ u32 b_base(u32 sb, int region, int ncol0, int lane) {
    return sb + (u32)region +
        (u32)(((ncol0 + (lane & 7) + ((lane & 16) ? 8 : 0)) * PITCH +
               ((lane & 8) ? 8 : 0)) * 2);
}

// ---------------------------------------------------------------------------
// wprep: W[k][n] fp32 -> Wt[n][k] bf16 hi/lo. grid=3 (Wq, Wk, Wv).
// ---------------------------------------------------------------------------
__global__ __launch_bounds__(256) void wprep_kernel(
    const float* __restrict__ Wq, const float* __restrict__ Wk,
    const float* __restrict__ Wv)
{
    const float* Wl[3] = {Wq, Wk, Wv};
    const float* W = Wl[blockIdx.x];
    __nv_bfloat16* hi = g_wt[blockIdx.x][0];
    __nv_bfloat16* lo = g_wt[blockIdx.x][1];
    for (int i = threadIdx.x; i < 128 * 128; i += 256) {
        int k = i >> 7, n = i & 127;
        float v = W[i];
        __nv_bfloat16 h = __float2bfloat16(v);
        __nv_bfloat16 l = __float2bfloat16(v - __bfloat162float(h));
        hi[n * PITCH + k] = h;
        lo[n * PITCH + k] = l;
    }
}

// ---------------------------------------------------------------------------
// KV + fused per-CTA KtV partial. 128-row tiles, 512 threads.
// QA: x split.  QB: Wk (prefetch) -> k split.  KS: Wv (prefetch) -> v split.
// ---------------------------------------------------------------------------
#define QA_HI 0
#define QA_LO 34816
#define QB_HI 69632
#define QB_LO 104448
#define KS_HI 139264
#define KS_LO 174080
#define QBIAS 208896
#define QKSUM 210432            // float[8][128]
#define SMEM_KV (QKSUM + 8 * 128 * 4)

__global__ __launch_bounds__(512, 1) void kv_kernel(
    const float* __restrict__ x,
    const float* __restrict__ bk, const float* __restrict__ bv)
{
    extern __shared__ char smem[];
    const u32 sb = smem_u32(smem);
    const int tid = threadIdx.x;
    const int wid = tid >> 5;
    const int lane = tid & 31;
    const int g = lane >> 2, c = lane & 3;
    const size_t row0 = (size_t)blockIdx.x * 128;

    float* sbias = (float*)(smem + QBIAS);
    float* sksum = (float*)(smem + QKSUM);
    if (tid < 128) {
        sbias[tid]       = bk[tid];
        sbias[128 + tid] = bv[tid];
    }

    // prefetch Wk -> QB, Wv -> KS (async, overlapped with x convert)
    {
        const uint4* wkh = (const uint4*)g_wt[1][0];
        const uint4* wkl = (const uint4*)g_wt[1][1];
        const uint4* wvh = (const uint4*)g_wt[2][0];
        const uint4* wvl = (const uint4*)g_wt[2][1];
#pragma unroll
        for (int i = 0; i < 5; ++i) {
            int idx = tid + i * 512;
            if (idx < 2176) {
                cp_async16(sb + QB_HI + idx * 16, wkh + idx);
                cp_async16(sb + QB_LO + idx * 16, wkl + idx);
                cp_async16(sb + KS_HI + idx * 16, wvh + idx);
                cp_async16(sb + KS_LO + idx * 16, wvl + idx);
            }
        }
        CP_COMMIT();
    }

    // load x tile, split hi/lo bf16 into QA
    {
        const float4* xg = reinterpret_cast<const float4*>(x + row0 * EDIM);
#pragma unroll
        for (int i = 0; i < 8; ++i) {
            int idx = tid + i * 512;
            int row = idx >> 5;
            int c4  = (idx & 31) << 2;
            float4 v = xg[idx];
            u32 h01 = pack_bf2(v.x, v.y);
            u32 h23 = pack_bf2(v.z, v.w);
            u32 l01 = pack_bf2(v.x - bf_lo(h01), v.y - bf_hi(h01));
            u32 l23 = pack_bf2(v.z - bf_lo(h23), v.w - bf_hi(h23));
            int off = (row * PITCH + c4) * 2;
            *(uint2*)(smem + QA_HI + off) = make_uint2(h01, h23);
            *(uint2*)(smem + QA_LO + off) = make_uint2(l01, l23);
        }
    }
    CP_WAIT0();
    __syncthreads();

    const int arow = (wid & 7) * 16;
    const int ncol0 = (wid >> 3) * 64;
    const int aw = wid & 7;

    const u32 aHi = a_base(sb, QA_HI, arow, lane);
    const u32 aLo = a_base(sb, QA_LO, arow, lane);
    const u32 bHiK = b_base(sb, QB_HI, ncol0, lane);
    const u32 bLoK = b_base(sb, QB_LO, ncol0, lane);
    const u32 bHiV = b_base(sb, KS_HI, ncol0, lane);
    const u32 bLoV = b_base(sb, KS_LO, ncol0, lane);

    // ---- k projection ----
    {
        float acc[8][4];
#pragma unroll
        for (int i = 0; i < 8; ++i)
#pragma unroll
            for (int j = 0; j < 4; ++j) acc[i][j] = 0.f;

        gemm3p_ldsm(aHi, aLo, bHiK, bLoK, acc);
        __syncthreads();   // all Wk reads done -> QB reusable

        // epilogue: bias + elu, split k -> QB; ksum partials
#pragma unroll
        for (int nt = 0; nt < 8; ++nt) {
            int col = ncol0 + nt * 8 + 2 * c;
            float2 bb = *(const float2*)(sbias + col);
            float k0x = elu1(acc[nt][0] + bb.x), k0y = elu1(acc[nt][1] + bb.y);
            float k1x = elu1(acc[nt][2] + bb.x), k1y = elu1(acc[nt][3] + bb.y);
            u32 h0 = pack_bf2(k0x, k0y);
            u32 h1 = pack_bf2(k1x, k1y);
            u32 l0 = pack_bf2(k0x - bf_lo(h0), k0y - bf_hi(h0));
            u32 l1 = pack_bf2(k1x - bf_lo(h1), k1y - bf_hi(h1));
            int o0 = ((arow + g) * PITCH + col) * 2;
            int o1 = ((arow + g + 8) * PITCH + col) * 2;
            *(u32*)(smem + QB_HI + o0) = h0;
            *(u32*)(smem + QB_LO + o0) = l0;
            *(u32*)(smem + QB_HI + o1) = h1;
            *(u32*)(smem + QB_LO + o1) = l1;
            float s0 = k0x + k1x;
            float s1 = k0y + k1y;
            s0 += __shfl_xor_sync(0xffffffffu, s0, 16);
            s0 += __shfl_xor_sync(0xffffffffu, s0, 8);
            s0 += __shfl_xor_sync(0xffffffffu, s0, 4);
            s1 += __shfl_xor_sync(0xffffffffu, s1, 16);
            s1 += __shfl_xor_sync(0xffffffffu, s1, 8);
            s1 += __shfl_xor_sync(0xffffffffu, s1, 4);
            if (lane < 4) {
                sksum[aw * 128 + col]     = s0;
                sksum[aw * 128 + col + 1] = s1;
            }
        }
    }

    // ---- v projection (Wv already resident in KS) ----
    {
        float acc[8][4];
#pragma unroll
        for (int i = 0; i < 8; ++i)
#pragma unroll
            for (int j = 0; j < 4; ++j) acc[i][j] = 0.f;

        gemm3p_ldsm(aHi, aLo, bHiV, bLoV, acc);

        const float* bias = sbias + 128;
#pragma unroll
        for (int nt = 0; nt < 8; ++nt) {
            int col = ncol0 + nt * 8 + 2 * c;
            float2 bb = *(const float2*)(bias + col);
            acc[nt][0] += bb.x; acc[nt][1] += bb.y;
            acc[nt][2] += bb.x; acc[nt][3] += bb.y;
        }
        __syncthreads();   // all Wv reads done -> KS reusable
#pragma unroll
        for (int nt = 0; nt < 8; ++nt) {
            int col = ncol0 + nt * 8 + 2 * c;
            u32 h0 = pack_bf2(acc[nt][0], acc[nt][1]);
            u32 h1 = pack_bf2(acc[nt][2], acc[nt][3]);
            u32 l0 = pack_bf2(acc[nt][0] - bf_lo(h0), acc[nt][1] - bf_hi(h0));
            u32 l1 = pack_bf2(acc[nt][2] - bf_lo(h1), acc[nt][3] - bf_hi(h1));
            int o0 = ((arow + g) * PITCH + col) * 2;
            int o1 = ((arow + g + 8) * PITCH + col) * 2;
            *(u32*)(smem + KS_HI + o0) = h0;
            *(u32*)(smem + KS_LO + o0) = l0;
            *(u32*)(smem + KS_HI + o1) = h1;
            *(u32*)(smem + KS_LO + o1) = l1;
        }
    }
    __syncthreads();   // k-split + v-split + sksum complete

    if (tid < 128) {
        float s = 0.f;
#pragma unroll
        for (int i = 0; i < 8; ++i) s += sksum[i * 128 + tid];
        g_part[(size_t)blockIdx.x * PART_STRIDE + 4096 + tid] = s;
    }

    // ---- KtV partial phase: a = k (QB), b = v (KS) ----
    {
        const int h  = wid & 3;
        const int mt = (wid >> 2) & 1;
        const int np = wid >> 3;
        const int d0 = h * 32 + mt * 16;
        const int e0 = h * 32 + np * 16;

        const u32 a_roff = (u32)(((lane & 7) + ((lane & 16) ? 8 : 0)) * (PITCH * 2));
        const u32 a_coff = (u32)((d0 + ((lane & 8) ? 8 : 0)) * 2);
        const u32 b_roff = (u32)(((lane & 7) + ((lane & 8) ? 8 : 0)) * (PITCH * 2));
        const u32 b_coff = (u32)((e0 + ((lane & 16) ? 8 : 0)) * 2);
        const u32 a_hi = sb + QB_HI + a_roff + a_coff;
        const u32 a_lo = sb + QB_LO + a_roff + a_coff;
        const u32 b_hi = sb + KS_HI + b_roff + b_coff;
        const u32 b_lo = sb + KS_LO + b_roff + b_coff;

        float acc[2][4];
#pragma unroll
        for (int i = 0; i < 2; ++i)
#pragma unroll
            for (int j = 0; j < 4; ++j) acc[i][j] = 0.f;

#pragma unroll
        for (int c0 = 0; c0 < 128; c0 += 16) {
            u32 off = (u32)(c0 * (PITCH * 2));
            u32 ah[4], al[4], bh[4], bl[4];
            ldsm_x4_t(ah, a_hi + off);
            ldsm_x4_t(al, a_lo + off);
            ldsm_x4_t(bh, b_hi + off);
            ldsm_x4_t(bl, b_lo + off);
            mma16816(acc[0], ah, bh[0], bh[1]);
            mma16816(acc[1], ah, bh[2], bh[3]);
            mma16816(acc[0], ah, bl[0], bl[1]);
            mma16816(acc[1], ah, bl[2], bl[3]);
            mma16816(acc[0], al, bh[0], bh[1]);
            mma16816(acc[1], al, bh[2], bh[3]);
        }

        float* dst = g_part + (size_t)blockIdx.x * PART_STRIDE + h * 1024;
#pragma unroll
        for (int nt = 0; nt < 2; ++nt) {
            int d_lo = mt * 16 + g;
            int e_lo = np * 16 + nt * 8 + 2 * c;
            *(float2*)&dst[d_lo * 32 + e_lo]       = make_float2(acc[nt][0], acc[nt][1]);
            *(float2*)&dst[(d_lo + 8) * 32 + e_lo] = make_float2(acc[nt][2], acc[nt][3]);
        }
    }
}

// ---------------------------------------------------------------------------
// fold: per (br,h): reduce 16 CTA partials -> KtV; ksum (h==0);
//       G[d][n] = sum_d' KtV[d][d']*Wo[h*32+d'][n] -> split bf16 [n][k].
// ---------------------------------------------------------------------------
__global__ __launch_bounds__(256) void fold_kernel(const float* __restrict__ Wo)
{
    __shared__ float ktv_s[1024];   // [e][d]
    __shared__ float ws[4096];      // Wo slice [32][128]

    const int tid = threadIdx.x;
    const int br  = blockIdx.x >> 2;
    const int h   = blockIdx.x & 3;
    const float* base = g_part + (size_t)br * 16 * PART_STRIDE;

    {
        float v0 = 0.f, v1 = 0.f, v2 = 0.f, v3 = 0.f;
#pragma unroll 4
        for (int i = 0; i < 16; ++i) {
            float4 p = *(const float4*)(base + (size_t)i * PART_STRIDE + h * 1024 + tid * 4);
            v0 += p.x; v1 += p.y; v2 += p.z; v3 += p.w;
        }
        int d = tid >> 3, e0 = (tid & 7) * 4;
        ktv_s[(e0 + 0) * 32 + d] = v0;
        ktv_s[(e0 + 1) * 32 + d] = v1;
        ktv_s[(e0 + 2) * 32 + d] = v2;
        ktv_s[(e0 + 3) * 32 + d] = v3;
    }

    if (h == 0 && tid < 128) {
        float s = 0.f;
#pragma unroll 4
        for (int i = 0; i < 16; ++i)
            s += base[(size_t)i * PART_STRIDE + 4096 + tid];
        g_ksum[(size_t)br * 128 + tid] = s;
    }

    {
        const float4* wg = reinterpret_cast<const float4*>(Wo + h * 4096);
#pragma unroll
        for (int i = 0; i < 4; ++i)
            reinterpret_cast<float4*>(ws)[tid + i * 256] = wg[tid + i * 256];
    }
    __syncthreads();

    {
        const int n  = tid >> 1;
        const int d0 = (tid & 1) * 16;
        float acc[16];
#pragma unroll
        for (int j = 0; j < 16; ++j) acc[j] = 0.f;
#pragma unroll 4
        for (int dp = 0; dp < 32; ++dp) {
            float w = ws[dp * 128 + n];
            const float4* kp = (const float4*)(ktv_s + dp * 32 + d0);
            float4 k0 = kp[0], k1 = kp[1], k2 = kp[2], k3 = kp[3];
            acc[0]  += w * k0.x; acc[1]  += w * k0.y; acc[2]  += w * k0.z; acc[3]  += w * k0.w;
            acc[4]  += w * k1.x; acc[5]  += w * k1.y; acc[6]  += w * k1.z; acc[7]  += w * k1.w;
            acc[8]  += w * k2.x; acc[9]  += w * k2.y; acc[10] += w * k2.z; acc[11] += w * k2.w;
            acc[12] += w * k3.x; acc[13] += w * k3.y; acc[14] += w * k3.z; acc[15] += w * k3.w;
        }
        __nv_bfloat16 hbuf[16], lbuf[16];
#pragma unroll
        for (int j = 0; j < 16; ++j) {
            __nv_bfloat16 hv = __float2bfloat16(acc[j]);
            hbuf[j] = hv;
            lbuf[j] = __float2bfloat16(acc[j] - __bfloat162float(hv));
        }
        int eo = n * PITCH + h * 32 + d0;
        uint4* dh = (uint4*)&g_G[br][0][eo];
        uint4* dl = (uint4*)&g_G[br][1][eo];
        dh[0] = ((uint4*)hbuf)[0]; dh[1] = ((uint4*)hbuf)[1];
        dl[0] = ((uint4*)lbuf)[0]; dl[1] = ((uint4*)lbuf)[1];
    }
}

// ---------------------------------------------------------------------------
// out: q = elu(x@Wq+bq); z = 1/(q.ksum+eps); out = sum_h z_h*(q_h@G_h) + bo.
// OA: x split -> q split.  OB: Wq (prefetch).  OG: G (prefetch).
// ---------------------------------------------------------------------------
#define OA_HI 0
#define OA_LO 34816
#define OB_HI 69632
#define OB_LO 104448
#define OG_HI 139264
#define OG_LO 174080
#define OKS   208896            // ksum 128f
#define OZ    209408            // z 512f
#define OBQ   211456            // bq 128f
#define OBO   211968            // bo 128f
#define SMEM_OUT (OBO + 512)

__global__ __launch_bounds__(512, 1) void out_kernel(
    const float* __restrict__ x, const float* __restrict__ bq,
    const float* __restrict__ bo, float* __restrict__ out)
{
    extern __shared__ char smem[];
    const u32 sb = smem_u32(smem);
    const int tid = threadIdx.x;
    const int wid = tid >> 5;
    const int lane = tid & 31;
    const int g = lane >> 2, c = lane & 3;
    const size_t row0 = (size_t)blockIdx.x * 128;
    const int br = blockIdx.x >> 4;

    float* ks_s = (float*)(smem + OKS);
    float* zs   = (float*)(smem + OZ);
    float* bq_s = (float*)(smem + OBQ);
    float* bo_s = (float*)(smem + OBO);

    if (tid < 128) ks_s[tid] = g_ksum[(size_t)br * 128 + tid];
    else if (tid < 256) bq_s[tid - 128] = bq[tid - 128];
    else if (tid < 384) bo_s[tid - 256] = bo[tid - 256];

    // prefetch Wq -> OB, G -> OG
    {
        const uint4* wqh = (const uint4*)g_wt[0][0];
        const uint4* wql = (const uint4*)g_wt[0][1];
        const uint4* gh  = (const uint4*)g_G[br][0];
        const uint4* gl  = (const uint4*)g_G[br][1];
#pragma unroll
        for (int i = 0; i < 5; ++i) {
            int idx = tid + i * 512;
            if (idx < 2176) {
                cp_async16(sb + OB_HI + idx * 16, wqh + idx);
                cp_async16(sb + OB_LO + idx * 16, wql + idx);
                cp_async16(sb + OG_HI + idx * 16, gh + idx);
                cp_async16(sb + OG_LO + idx * 16, gl + idx);
            }
        }
        CP_COMMIT();
    }

    // load x tile split into OA
    {
        const float4* xg = reinterpret_cast<const float4*>(x + row0 * EDIM);
#pragma unroll
        for (int i = 0; i < 8; ++i) {
            int idx = tid + i * 512;
            int row = idx >> 5;
            int c4  = (idx & 31) << 2;
            float4 v = xg[idx];
            u32 h01 = pack_bf2(v.x, v.y);
            u32 h23 = pack_bf2(v.z, v.w);
            u32 l01 = pack_bf2(v.x - bf_lo(h01), v.y - bf_hi(h01));
            u32 l23 = pack_bf2(v.z - bf_lo(h23), v.w - bf_hi(h23));
            int off = (row * PITCH + c4) * 2;
            *(uint2*)(smem + OA_HI + off) = make_uint2(h01, h23);
            *(uint2*)(smem + OA_LO + off) = make_uint2(l01, l23);
        }
    }
    CP_WAIT0();
    __syncthreads();

    const int arow = (wid & 7) * 16;
    const int ncol0 = (wid >> 3) * 64;
    const u32 aHi = a_base(sb, OA_HI, arow, lane);
    const u32 aLo = a_base(sb, OA_LO, arow, lane);
    const u32 bHiW = b_base(sb, OB_HI, ncol0, lane);
    const u32 bLoW = b_base(sb, OB_LO, ncol0, lane);
    const u32 bHiG = b_base(sb, OG_HI, ncol0, lane);
    const u32 bLoG = b_base(sb, OG_LO, ncol0, lane);

    // q = x @ Wq (3-pass)
    float qa[8][4];
#pragma unroll
    for (int i = 0; i < 8; ++i)
#pragma unroll
        for (int j = 0; j < 4; ++j) qa[i][j] = 0.f;
    gemm3p_ldsm(aHi, aLo, bHiW, bLoW, qa);

    __syncthreads();   // all x reads (OA) done

    // bias + elu, split q fragments into OA
#pragma unroll
    for (int nt = 0; nt < 8; ++nt) {
        int col = ncol0 + nt * 8 + 2 * c;
        float2 bb = *(const float2*)(bq_s + col);
        float q0x = elu1(qa[nt][0] + bb.x), q0y = elu1(qa[nt][1] + bb.y);
        float q1x = elu1(qa[nt][2] + bb.x), q1y = elu1(qa[nt][3] + bb.y);
        u32 h0 = pack_bf2(q0x, q0y);
        u32 h1 = pack_bf2(q1x, q1y);
        u32 l0 = pack_bf2(q0x - bf_lo(h0), q0y - bf_hi(h0));
        u32 l1 = pack_bf2(q1x - bf_lo(h1), q1y - bf_hi(h1));
        int o0 = ((arow + g) * PITCH + col) * 2;
        int o1 = ((arow + g + 8) * PITCH + col) * 2;
        *(u32*)(smem + OA_HI + o0) = h0;
        *(u32*)(smem + OA_LO + o0) = l0;
        *(u32*)(smem + OA_HI + o1) = h1;
        *(u32*)(smem + OA_LO + o1) = l1;
    }
    __syncthreads();   // q split complete

    // z per (row, head)
    {
        const int row = tid >> 2;
        const int h   = tid & 3;
        const u32 bh0 = (u32)((row * PITCH + h * 32) * 2);
        const float* ksp = ks_s + h * 32;
        float dot = 0.f;
#pragma unroll
        for (int i = 0; i < 16; ++i) {
            u32 uh = *(const u32*)(smem + OA_HI + bh0 + i * 4);
            u32 ul = *(const u32*)(smem + OA_LO + bh0 + i * 4);
            dot += (bf_lo(uh) + bf_lo(ul)) * ksp[2 * i];
            dot += (bf_hi(uh) + bf_hi(ul)) * ksp[2 * i + 1];
        }
        zs[row * 4 + h] = 1.f / (dot + 1e-6f);
    }
    __syncthreads();

    // out = sum_h z_h * (q_h @ G_h) + bo
    {
        float acc[8][4];
#pragma unroll
        for (int i = 0; i < 8; ++i)
#pragma unroll
            for (int j = 0; j < 4; ++j) acc[i][j] = 0.f;

#pragma unroll
        for (int h = 0; h < 4; ++h) {
            float pacc[8][4];
#pragma unroll
            for (int i = 0; i < 8; ++i)
#pragma unroll
                for (int j = 0; j < 4; ++j) pacc[i][j] = 0.f;

#pragma unroll
            for (int ks = 0; ks < 2; ++ks) {
                const u32 koff = (u32)((h * 32 + ks * 16) * 2);
                u32 ah[4], al[4];
                ldsm_x4(ah, aHi + koff);
                ldsm_x4(al, aLo + koff);
#pragma unroll
                for (int np = 0; np < 4; ++np) {
                    const u32 boff = koff + (u32)(np * 16 * PITCH * 2);
                    u32 bh[4], bl[4];
                    ldsm_x4(bh, bHiG + boff);
                    ldsm_x4(bl, bLoG + boff);
                    mma16816(pacc[2 * np],     ah, bh[0], bh[1]);
                    mma16816(pacc[2 * np],     ah, bl[0], bl[1]);
                    mma16816(pacc[2 * np],     al, bh[0], bh[1]);
                    mma16816(pacc[2 * np + 1], ah, bh[2], bh[3]);
                    mma16816(pacc[2 * np + 1], ah, bl[2], bl[3]);
                    mma16816(pacc[2 * np + 1], al, bh[2], bh[3]);
                }
            }
            float z0 = zs[(arow + g) * 4 + h];
            float z1 = zs[(arow + g + 8) * 4 + h];
#pragma unroll
            for (int nt = 0; nt < 8; ++nt) {
                acc[nt][0] += z0 * pacc[nt][0];
                acc[nt][1] += z0 * pacc[nt][1];
                acc[nt][2] += z1 * pacc[nt][2];
                acc[nt][3] += z1 * pacc[nt][3];
            }
        }

#pragma unroll
        for (int nt = 0; nt < 8; ++nt) {
            int col = ncol0 + nt * 8 + 2 * c;
            float2 bb = *(const float2*)(bo_s + col);
            float2 r0, r1;
            r0.x = acc[nt][0] + bb.x; r0.y = acc[nt][1] + bb.y;
            r1.x = acc[nt][2] + bb.x; r1.y = acc[nt][3] + bb.y;
            size_t ra = row0 + arow + g;
            *(float2*)(out + ra * EDIM + col)       = r0;
            *(float2*)(out + (ra + 8) * EDIM + col) = r1;
        }
    }
}

// ---------------------------------------------------------------------------
extern "C" void kernel_launch(void* const* d_in, const int* in_sizes, int n_in,
                              void* d_out, int out_size)
{
    const float* x  = (const float*)d_in[0];
    const float* Wq = (const float*)d_in[1];
    const float* bq = (const float*)d_in[2];
    const float* Wk = (const float*)d_in[3];
    const float* bk = (const float*)d_in[4];
    const float* Wv = (const float*)d_in[5];
    const float* bv = (const float*)d_in[6];
    const float* Wo = (const float*)d_in[7];
    const float* bo = (const float*)d_in[8];
    float* out = (float*)d_out;

    cudaFuncSetAttribute(kv_kernel, cudaFuncAttributeMaxDynamicSharedMemorySize, SMEM_KV);
    cudaFuncSetAttribute(out_kernel, cudaFuncAttributeMaxDynamicSharedMemorySize, SMEM_OUT);

    wprep_kernel<<<3, 256>>>(Wq, Wk, Wv);
    kv_kernel<<<NCTA, 512, SMEM_KV>>>(x, bk, bv);
    fold_kernel<<<NBR * HEADS, 256>>>(Wo);
    out_kernel<<<NCTA, 512, SMEM_OUT>>>(x, bq, bo, out);
}

// round 12
// speedup vs baseline: 1.1203x; 1.0396x over previous
#include <cuda_runtime.h>
#include <cuda_bf16.h>
#include <cstdint>

#define BATCH 2
#define RDIM  64
#define CDIM  2048
#define EDIM  128
#define HEADS 4
#define DHEAD 32
#define NROWS (BATCH*RDIM*CDIM)      // 262144
#define NBR   (BATCH*RDIM)           // 128
#define NCTA  (NROWS/128)            // 2048
#define PART_STRIDE 4224

#define PITCH 136                     // bf16 elements per row

typedef unsigned int u32;

// Scratch (device globals)
__device__ float g_ksum[(size_t)NBR * HEADS * DHEAD];
__device__ __align__(16) float g_part[(size_t)NCTA * PART_STRIDE];
__device__ __align__(16) __nv_bfloat16 g_G[NBR][2][128 * PITCH];
__device__ __align__(16) __nv_bfloat16 g_wt[3][2][128 * PITCH];
// Split x, per-CTA tile, byte-identical to the smem OA region layout
__device__ __align__(16) __nv_bfloat16 g_xs[NCTA][2][128 * PITCH];

__device__ __forceinline__ float elu1(float x) {
    return x > 0.f ? x + 1.f : expf(x);
}

__device__ __forceinline__ void mma16816(float* d, const u32* a, u32 b0, u32 b1) {
    asm volatile(
        "mma.sync.aligned.m16n8k16.row.col.f32.bf16.bf16.f32 "
        "{%0,%1,%2,%3}, {%4,%5,%6,%7}, {%8,%9}, {%0,%1,%2,%3};"
        : "+f"(d[0]), "+f"(d[1]), "+f"(d[2]), "+f"(d[3])
        : "r"(a[0]), "r"(a[1]), "r"(a[2]), "r"(a[3]), "r"(b0), "r"(b1));
}

__device__ __forceinline__ void ldsm_x4(u32* r, u32 addr) {
    asm volatile("ldmatrix.sync.aligned.m8n8.x4.shared.b16 {%0,%1,%2,%3}, [%4];"
        : "=r"(r[0]), "=r"(r[1]), "=r"(r[2]), "=r"(r[3]) : "r"(addr));
}

__device__ __forceinline__ void ldsm_x4_t(u32* r, u32 addr) {
    asm volatile("ldmatrix.sync.aligned.m8n8.x4.trans.shared.b16 {%0,%1,%2,%3}, [%4];"
        : "=r"(r[0]), "=r"(r[1]), "=r"(r[2]), "=r"(r[3]) : "r"(addr));
}

__device__ __forceinline__ uint32_t smem_u32(const void* p) {
    uint32_t a;
    asm("{ .reg .u64 t; cvta.to.shared.u64 t, %1; cvt.u32.u64 %0, t; }" : "=r"(a) : "l"(p));
    return a;
}

__device__ __forceinline__ void cp_async16(u32 saddr, const void* gptr) {
    asm volatile("cp.async.cg.shared.global [%0], [%1], 16;"
        :: "r"(saddr), "l"(gptr));
}
#define CP_COMMIT() asm volatile("cp.async.commit_group;" ::: "memory")
#define CP_WAIT0()  asm volatile("cp.async.wait_group 0;" ::: "memory")

__device__ __forceinline__ u32 pack_bf2(float x, float y) {
    __nv_bfloat162 p = __floats2bfloat162_rn(x, y);
    return *(u32*)&p;
}
__device__ __forceinline__ float bf_lo(u32 u) {
    return __bfloat162float(*(__nv_bfloat16*)&u);
}
__device__ __forceinline__ float bf_hi(u32 u) {
    return __bfloat162float(((__nv_bfloat16*)&u)[1]);
}

// 3-pass split GEMM (acc-major order — proven fastest).
__device__ __forceinline__ void gemm3p_ldsm(
    u32 aHi, u32 aLo, u32 bHi, u32 bLo, float acc[8][4])
{
#pragma unroll
    for (int k0 = 0; k0 < 128; k0 += 16) {
        const u32 koff = (u32)(k0 * 2);
        u32 ah[4], al[4];
        ldsm_x4(ah, aHi + koff);
        ldsm_x4(al, aLo + koff);
#pragma unroll
        for (int np = 0; np < 4; ++np) {
            const u32 boff = koff + (u32)(np * 16 * PITCH * 2);
            u32 bh[4], bl[4];
            ldsm_x4(bh, bHi + boff);
            ldsm_x4(bl, bLo + boff);
            mma16816(acc[2 * np],     ah, bh[0], bh[1]);
            mma16816(acc[2 * np],     ah, bl[0], bl[1]);
            mma16816(acc[2 * np],     al, bh[0], bh[1]);
            mma16816(acc[2 * np + 1], ah, bh[2], bh[3]);
            mma16816(acc[2 * np + 1], ah, bl[2], bl[3]);
            mma16816(acc[2 * np + 1], al, bh[2], bh[3]);
        }
    }
}

__device__ __forceinline__ u32 a_base(u32 sb, int region, int arow, int lane) {
    return sb + (u32)region +
        (u32)(((arow + (lane & 15)) * PITCH + ((lane & 16) ? 8 : 0)) * 2);
}
__device__ __forceinline__ u32 b_base(u32 sb, int region, int ncol0, int lane) {
    return sb + (u32)region +
        (u32)(((ncol0 + (lane & 7) + ((lane & 16) ? 8 : 0)) * PITCH +
               ((lane & 8) ? 8 : 0)) * 2);
}

// ---------------------------------------------------------------------------
// wprep: W[k][n] fp32 -> Wt[n][k] bf16 hi/lo. grid=3 (Wq, Wk, Wv).
// ---------------------------------------------------------------------------
__global__ __launch_bounds__(256) void wprep_kernel(
    const float* __restrict__ Wq, const float* __restrict__ Wk,
    const float* __restrict__ Wv)
{
    const float* Wl[3] = {Wq, Wk, Wv};
    const float* W = Wl[blockIdx.x];
    __nv_bfloat16* hi = g_wt[blockIdx.x][0];
    __nv_bfloat16* lo = g_wt[blockIdx.x][1];
    for (int i = threadIdx.x; i < 128 * 128; i += 256) {
        int k = i >> 7, n = i & 127;
        float v = W[i];
        __nv_bfloat16 h = __float2bfloat16(v);
        __nv_bfloat16 l = __float2bfloat16(v - __bfloat162float(h));
        hi[n * PITCH + k] = h;
        lo[n * PITCH + k] = l;
    }
}

// ---------------------------------------------------------------------------
// KV + fused per-CTA KtV partial + split-x export. 128-row tiles, 512 threads.
// ---------------------------------------------------------------------------
#define QA_HI 0
#define QA_LO 34816
#define QB_HI 69632
#define QB_LO 104448
#define KS_HI 139264
#define KS_LO 174080
#define QBIAS 208896
#define QKSUM 210432            // float[8][128]
#define SMEM_KV (QKSUM + 8 * 128 * 4)

__global__ __launch_bounds__(512, 1) void kv_kernel(
    const float* __restrict__ x,
    const float* __restrict__ bk, const float* __restrict__ bv)
{
    extern __shared__ char smem[];
    const u32 sb = smem_u32(smem);
    const int tid = threadIdx.x;
    const int wid = tid >> 5;
    const int lane = tid & 31;
    const int g = lane >> 2, c = lane & 3;
    const size_t row0 = (size_t)blockIdx.x * 128;

    float* sbias = (float*)(smem + QBIAS);
    float* sksum = (float*)(smem + QKSUM);
    if (tid < 128) {
        sbias[tid]       = bk[tid];
        sbias[128 + tid] = bv[tid];
    }

    // prefetch Wk -> QB, Wv -> KS (async, overlapped with x convert)
    {
        const uint4* wkh = (const uint4*)g_wt[1][0];
        const uint4* wkl = (const uint4*)g_wt[1][1];
        const uint4* wvh = (const uint4*)g_wt[2][0];
        const uint4* wvl = (const uint4*)g_wt[2][1];
#pragma unroll
        for (int i = 0; i < 5; ++i) {
            int idx = tid + i * 512;
            if (idx < 2176) {
                cp_async16(sb + QB_HI + idx * 16, wkh + idx);
                cp_async16(sb + QB_LO + idx * 16, wkl + idx);
                cp_async16(sb + KS_HI + idx * 16, wvh + idx);
                cp_async16(sb + KS_LO + idx * 16, wvl + idx);
            }
        }
        CP_COMMIT();
    }

    // load x tile, split hi/lo bf16 into QA + export to g_xs (same values)
    {
        const float4* xg = reinterpret_cast<const float4*>(x + row0 * EDIM);
        char* xs_hi = (char*)g_xs[blockIdx.x][0];
        char* xs_lo = (char*)g_xs[blockIdx.x][1];
#pragma unroll
        for (int i = 0; i < 8; ++i) {
            int idx = tid + i * 512;
            int row = idx >> 5;
            int c4  = (idx & 31) << 2;
            float4 v = xg[idx];
            u32 h01 = pack_bf2(v.x, v.y);
            u32 h23 = pack_bf2(v.z, v.w);
            u32 l01 = pack_bf2(v.x - bf_lo(h01), v.y - bf_hi(h01));
            u32 l23 = pack_bf2(v.z - bf_lo(h23), v.w - bf_hi(h23));
            int off = (row * PITCH + c4) * 2;
            uint2 hh = make_uint2(h01, h23);
            uint2 ll = make_uint2(l01, l23);
            *(uint2*)(smem + QA_HI + off) = hh;
            *(uint2*)(smem + QA_LO + off) = ll;
            *(uint2*)(xs_hi + off) = hh;    // fire-and-forget export
            *(uint2*)(xs_lo + off) = ll;
        }
    }
    CP_WAIT0();
    __syncthreads();

    const int arow = (wid & 7) * 16;
    const int ncol0 = (wid >> 3) * 64;
    const int aw = wid & 7;

    const u32 aHi = a_base(sb, QA_HI, arow, lane);
    const u32 aLo = a_base(sb, QA_LO, arow, lane);
    const u32 bHiK = b_base(sb, QB_HI, ncol0, lane);
    const u32 bLoK = b_base(sb, QB_LO, ncol0, lane);
    const u32 bHiV = b_base(sb, KS_HI, ncol0, lane);
    const u32 bLoV = b_base(sb, KS_LO, ncol0, lane);

    // ---- k projection ----
    {
        float acc[8][4];
#pragma unroll
        for (int i = 0; i < 8; ++i)
#pragma unroll
            for (int j = 0; j < 4; ++j) acc[i][j] = 0.f;

        gemm3p_ldsm(aHi, aLo, bHiK, bLoK, acc);
        __syncthreads();   // all Wk reads done -> QB reusable

        // epilogue: bias + elu, split k -> QB; ksum partials
#pragma unroll
        for (int nt = 0; nt < 8; ++nt) {
            int col = ncol0 + nt * 8 + 2 * c;
            float2 bb = *(const float2*)(sbias + col);
            float k0x = elu1(acc[nt][0] + bb.x), k0y = elu1(acc[nt][1] + bb.y);
            float k1x = elu1(acc[nt][2] + bb.x), k1y = elu1(acc[nt][3] + bb.y);
            u32 h0 = pack_bf2(k0x, k0y);
            u32 h1 = pack_bf2(k1x, k1y);
            u32 l0 = pack_bf2(k0x - bf_lo(h0), k0y - bf_hi(h0));
            u32 l1 = pack_bf2(k1x - bf_lo(h1), k1y - bf_hi(h1));
            int o0 = ((arow + g) * PITCH + col) * 2;
            int o1 = ((arow + g + 8) * PITCH + col) * 2;
            *(u32*)(smem + QB_HI + o0) = h0;
            *(u32*)(smem + QB_LO + o0) = l0;
            *(u32*)(smem + QB_HI + o1) = h1;
            *(u32*)(smem + QB_LO + o1) = l1;
            float s0 = k0x + k1x;
            float s1 = k0y + k1y;
            s0 += __shfl_xor_sync(0xffffffffu, s0, 16);
            s0 += __shfl_xor_sync(0xffffffffu, s0, 8);
            s0 += __shfl_xor_sync(0xffffffffu, s0, 4);
            s1 += __shfl_xor_sync(0xffffffffu, s1, 16);
            s1 += __shfl_xor_sync(0xffffffffu, s1, 8);
            s1 += __shfl_xor_sync(0xffffffffu, s1, 4);
            if (lane < 4) {
                sksum[aw * 128 + col]     = s0;
                sksum[aw * 128 + col + 1] = s1;
            }
        }
    }

    // ---- v projection (Wv already resident in KS) ----
    {
        float acc[8][4];
#pragma unroll
        for (int i = 0; i < 8; ++i)
#pragma unroll
            for (int j = 0; j < 4; ++j) acc[i][j] = 0.f;

        gemm3p_ldsm(aHi, aLo, bHiV, bLoV, acc);

        const float* bias = sbias + 128;
#pragma unroll
        for (int nt = 0; nt < 8; ++nt) {
            int col = ncol0 + nt * 8 + 2 * c;
            float2 bb = *(const float2*)(bias + col);
            acc[nt][0] += bb.x; acc[nt][1] += bb.y;
            acc[nt][2] += bb.x; acc[nt][3] += bb.y;
        }
        __syncthreads();   // all Wv reads done -> KS reusable
#pragma unroll
        for (int nt = 0; nt < 8; ++nt) {
            int col = ncol0 + nt * 8 + 2 * c;
            u32 h0 = pack_bf2(acc[nt][0], acc[nt][1]);
            u32 h1 = pack_bf2(acc[nt][2], acc[nt][3]);
            u32 l0 = pack_bf2(acc[nt][0] - bf_lo(h0), acc[nt][1] - bf_hi(h0));
            u32 l1 = pack_bf2(acc[nt][2] - bf_lo(h1), acc[nt][3] - bf_hi(h1));
            int o0 = ((arow + g) * PITCH + col) * 2;
            int o1 = ((arow + g + 8) * PITCH + col) * 2;
            *(u32*)(smem + KS_HI + o0) = h0;
            *(u32*)(smem + KS_LO + o0) = l0;
            *(u32*)(smem + KS_HI + o1) = h1;
            *(u32*)(smem + KS_LO + o1) = l1;
        }
    }
    __syncthreads();   // k-split + v-split + sksum complete

    if (tid < 128) {
        float s = 0.f;
#pragma unroll
        for (int i = 0; i < 8; ++i) s += sksum[i * 128 + tid];
        g_part[(size_t)blockIdx.x * PART_STRIDE + 4096 + tid] = s;
    }

    // ---- KtV partial phase: a = k (QB), b = v (KS) ----
    {
        const int h  = wid & 3;
        const int mt = (wid >> 2) & 1;
        const int np = wid >> 3;
        const int d0 = h * 32 + mt * 16;
        const int e0 = h * 32 + np * 16;

        const u32 a_roff = (u32)(((lane & 7) + ((lane & 16) ? 8 : 0)) * (PITCH * 2));
        const u32 a_coff = (u32)((d0 + ((lane & 8) ? 8 : 0)) * 2);
        const u32 b_roff = (u32)(((lane & 7) + ((lane & 8) ? 8 : 0)) * (PITCH * 2));
        const u32 b_coff = (u32)((e0 + ((lane & 16) ? 8 : 0)) * 2);
        const u32 a_hi = sb + QB_HI + a_roff + a_coff;
        const u32 a_lo = sb + QB_LO + a_roff + a_coff;
        const u32 b_hi = sb + KS_HI + b_roff + b_coff;
        const u32 b_lo = sb + KS_LO + b_roff + b_coff;

        float acc[2][4];
#pragma unroll
        for (int i = 0; i < 2; ++i)
#pragma unroll
            for (int j = 0; j < 4; ++j) acc[i][j] = 0.f;

#pragma unroll
        for (int c0 = 0; c0 < 128; c0 += 16) {
            u32 off = (u32)(c0 * (PITCH * 2));
            u32 ah[4], al[4], bh[4], bl[4];
            ldsm_x4_t(ah, a_hi + off);
            ldsm_x4_t(al, a_lo + off);
            ldsm_x4_t(bh, b_hi + off);
            ldsm_x4_t(bl, b_lo + off);
            mma16816(acc[0], ah, bh[0], bh[1]);
            mma16816(acc[1], ah, bh[2], bh[3]);
            mma16816(acc[0], ah, bl[0], bl[1]);
            mma16816(acc[1], ah, bl[2], bl[3]);
            mma16816(acc[0], al, bh[0], bh[1]);
            mma16816(acc[1], al, bh[2], bh[3]);
        }

        float* dst = g_part + (size_t)blockIdx.x * PART_STRIDE + h * 1024;
#pragma unroll
        for (int nt = 0; nt < 2; ++nt) {
            int d_lo = mt * 16 + g;
            int e_lo = np * 16 + nt * 8 + 2 * c;
            *(float2*)&dst[d_lo * 32 + e_lo]       = make_float2(acc[nt][0], acc[nt][1]);
            *(float2*)&dst[(d_lo + 8) * 32 + e_lo] = make_float2(acc[nt][2], acc[nt][3]);
        }
    }
}

// ---------------------------------------------------------------------------
// fold: per (br,h): reduce 16 CTA partials -> KtV; ksum (h==0);
//       G[d][n] = sum_d' KtV[d][d']*Wo[h*32+d'][n] -> split bf16 [n][k].
// ---------------------------------------------------------------------------
__global__ __launch_bounds__(256) void fold_kernel(const float* __restrict__ Wo)
{
    __shared__ float ktv_s[1024];   // [e][d]
    __shared__ float ws[4096];      // Wo slice [32][128]

    const int tid = threadIdx.x;
    const int br  = blockIdx.x >> 2;
    const int h   = blockIdx.x & 3;
    const float* base = g_part + (size_t)br * 16 * PART_STRIDE;

    {
        float v0 = 0.f, v1 = 0.f, v2 = 0.f, v3 = 0.f;
#pragma unroll 4
        for (int i = 0; i < 16; ++i) {
            float4 p = *(const float4*)(base + (size_t)i * PART_STRIDE + h * 1024 + tid * 4);
            v0 += p.x; v1 += p.y; v2 += p.z; v3 += p.w;
        }
        int d = tid >> 3, e0 = (tid & 7) * 4;
        ktv_s[(e0 + 0) * 32 + d] = v0;
        ktv_s[(e0 + 1) * 32 + d] = v1;
        ktv_s[(e0 + 2) * 32 + d] = v2;
        ktv_s[(e0 + 3) * 32 + d] = v3;
    }

    if (h == 0 && tid < 128) {
        float s = 0.f;
#pragma unroll 4
        for (int i = 0; i < 16; ++i)
            s += base[(size_t)i * PART_STRIDE + 4096 + tid];
        g_ksum[(size_t)br * 128 + tid] = s;
    }

    {
        const float4* wg = reinterpret_cast<const float4*>(Wo + h * 4096);
#pragma unroll
        for (int i = 0; i < 4; ++i)
            reinterpret_cast<float4*>(ws)[tid + i * 256] = wg[tid + i * 256];
    }
    __syncthreads();

    {
        const int n  = tid >> 1;
        const int d0 = (tid & 1) * 16;
        float acc[16];
#pragma unroll
        for (int j = 0; j < 16; ++j) acc[j] = 0.f;
#pragma unroll 4
        for (int dp = 0; dp < 32; ++dp) {
            float w = ws[dp * 128 + n];
            const float4* kp = (const float4*)(ktv_s + dp * 32 + d0);
            float4 k0 = kp[0], k1 = kp[1], k2 = kp[2], k3 = kp[3];
            acc[0]  += w * k0.x; acc[1]  += w * k0.y; acc[2]  += w * k0.z; acc[3]  += w * k0.w;
            acc[4]  += w * k1.x; acc[5]  += w * k1.y; acc[6]  += w * k1.z; acc[7]  += w * k1.w;
            acc[8]  += w * k2.x; acc[9]  += w * k2.y; acc[10] += w * k2.z; acc[11] += w * k2.w;
            acc[12] += w * k3.x; acc[13] += w * k3.y; acc[14] += w * k3.z; acc[15] += w * k3.w;
        }
        __nv_bfloat16 hbuf[16], lbuf[16];
#pragma unroll
        for (int j = 0; j < 16; ++j) {
            __nv_bfloat16 hv = __float2bfloat16(acc[j]);
            hbuf[j] = hv;
            lbuf[j] = __float2bfloat16(acc[j] - __bfloat162float(hv));
        }
        int eo = n * PITCH + h * 32 + d0;
        uint4* dh = (uint4*)&g_G[br][0][eo];
        uint4* dl = (uint4*)&g_G[br][1][eo];
        dh[0] = ((uint4*)hbuf)[0]; dh[1] = ((uint4*)hbuf)[1];
        dl[0] = ((uint4*)lbuf)[0]; dl[1] = ((uint4*)lbuf)[1];
    }
}

// ---------------------------------------------------------------------------
// out: q = elu(xs@Wq+bq); z folded into q epilogue; out = sum_h z_h*(q_h@G_h)+bo.
// OA: xs (cp.async) -> q split.  OB: Wq (cp.async).  OG: G (cp.async).
// ---------------------------------------------------------------------------
#define OA_HI 0
#define OA_LO 34816
#define OB_HI 69632
#define OB_LO 104448
#define OG_HI 139264
#define OG_LO 174080
#define OKS   208896            // ksum 128f
#define OZ    209408            // z 512f
#define OBQ   211456            // bq 128f
#define OBO   211968            // bo 128f
#define SMEM_OUT (OBO + 512)

__global__ __launch_bounds__(512, 1) void out_kernel(
    const float* __restrict__ bq,
    const float* __restrict__ bo, float* __restrict__ out)
{
    extern __shared__ char smem[];
    const u32 sb = smem_u32(smem);
    const int tid = threadIdx.x;
    const int wid = tid >> 5;
    const int lane = tid & 31;
    const int g = lane >> 2, c = lane & 3;
    const size_t row0 = (size_t)blockIdx.x * 128;
    const int br = blockIdx.x >> 4;

    float* ks_s = (float*)(smem + OKS);
    float* zs   = (float*)(smem + OZ);
    float* bq_s = (float*)(smem + OBQ);
    float* bo_s = (float*)(smem + OBO);

    // prefetch xs -> OA, Wq -> OB, G -> OG (everything async)
    {
        const uint4* xsh = (const uint4*)g_xs[blockIdx.x][0];
        const uint4* xsl = (const uint4*)g_xs[blockIdx.x][1];
        const uint4* wqh = (const uint4*)g_wt[0][0];
        const uint4* wql = (const uint4*)g_wt[0][1];
        const uint4* gh  = (const uint4*)g_G[br][0];
        const uint4* gl  = (const uint4*)g_G[br][1];
#pragma unroll
        for (int i = 0; i < 5; ++i) {
            int idx = tid + i * 512;
            if (idx < 2176) {
                cp_async16(sb + OA_HI + idx * 16, xsh + idx);
                cp_async16(sb + OA_LO + idx * 16, xsl + idx);
                cp_async16(sb + OB_HI + idx * 16, wqh + idx);
                cp_async16(sb + OB_LO + idx * 16, wql + idx);
                cp_async16(sb + OG_HI + idx * 16, gh + idx);
                cp_async16(sb + OG_LO + idx * 16, gl + idx);
            }
        }
        CP_COMMIT();
    }

    if (tid < 128) ks_s[tid] = g_ksum[(size_t)br * 128 + tid];
    else if (tid < 256) bq_s[tid - 128] = bq[tid - 128];
    else if (tid < 384) bo_s[tid - 256] = bo[tid - 256];

    CP_WAIT0();
    __syncthreads();

    const int arow = (wid & 7) * 16;
    const int ncol0 = (wid >> 3) * 64;
    const u32 aHi = a_base(sb, OA_HI, arow, lane);
    const u32 aLo = a_base(sb, OA_LO, arow, lane);
    const u32 bHiW = b_base(sb, OB_HI, ncol0, lane);
    const u32 bLoW = b_base(sb, OB_LO, ncol0, lane);
    const u32 bHiG = b_base(sb, OG_HI, ncol0, lane);
    const u32 bLoG = b_base(sb, OG_LO, ncol0, lane);

    // q = xs @ Wq (3-pass)
    float qa[8][4];
#pragma unroll
    for (int i = 0; i < 8; ++i)
#pragma unroll
        for (int j = 0; j < 4; ++j) qa[i][j] = 0.f;
    gemm3p_ldsm(aHi, aLo, bHiW, bLoW, qa);

    __syncthreads();   // all xs reads (OA) done

    // epilogue: bias + elu, split q into OA, fold z-dot accumulation
    {
        float d00 = 0.f, d01 = 0.f, d10 = 0.f, d11 = 0.f;
#pragma unroll
        for (int nt = 0; nt < 8; ++nt) {
            int col = ncol0 + nt * 8 + 2 * c;
            float2 bb = *(const float2*)(bq_s + col);
            float q0x = elu1(qa[nt][0] + bb.x), q0y = elu1(qa[nt][1] + bb.y);
            float q1x = elu1(qa[nt][2] + bb.x), q1y = elu1(qa[nt][3] + bb.y);
            float2 kk = *(const float2*)(ks_s + col);
            float t0 = q0x * kk.x + q0y * kk.y;
            float t1 = q1x * kk.x + q1y * kk.y;
            if (nt < 4) { d00 += t0; d10 += t1; }
            else        { d01 += t0; d11 += t1; }
            u32 h0 = pack_bf2(q0x, q0y);
            u32 h1 = pack_bf2(q1x, q1y);
            u32 l0 = pack_bf2(q0x - bf_lo(h0), q0y - bf_hi(h0));
            u32 l1 = pack_bf2(q1x - bf_lo(h1), q1y - bf_hi(h1));
            int o0 = ((arow + g) * PITCH + col) * 2;
            int o1 = ((arow + g + 8) * PITCH + col) * 2;
            *(u32*)(smem + OA_HI + o0) = h0;
            *(u32*)(smem + OA_LO + o0) = l0;
            *(u32*)(smem + OA_HI + o1) = h1;
            *(u32*)(smem + OA_LO + o1) = l1;
        }
        // quad reduce over c (lanes g*4+c)
        d00 += __shfl_xor_sync(0xffffffffu, d00, 1);
        d00 += __shfl_xor_sync(0xffffffffu, d00, 2);
        d01 += __shfl_xor_sync(0xffffffffu, d01, 1);
        d01 += __shfl_xor_sync(0xffffffffu, d01, 2);
        d10 += __shfl_xor_sync(0xffffffffu, d10, 1);
        d10 += __shfl_xor_sync(0xffffffffu, d10, 2);
        d11 += __shfl_xor_sync(0xffffffffu, d11, 1);
        d11 += __shfl_xor_sync(0xffffffffu, d11, 2);
        if (c == 0) {
            int h0 = ncol0 >> 5;   // 0 or 2
            zs[(arow + g) * 4 + h0]         = d00;
            zs[(arow + g) * 4 + h0 + 1]     = d01;
            zs[(arow + g + 8) * 4 + h0]     = d10;
            zs[(arow + g + 8) * 4 + h0 + 1] = d11;
        }
    }
    __syncthreads();   // q split + raw dots visible

    zs[tid] = 1.f / (zs[tid] + 1e-6f);
    __syncthreads();

    // out = sum_h z_h * (q_h @ G_h) + bo
    {
        float acc[8][4];
#pragma unroll
        for (int i = 0; i < 8; ++i)
#pragma unroll
            for (int j = 0; j < 4; ++j) acc[i][j] = 0.f;

#pragma unroll
        for (int h = 0; h < 4; ++h) {
            float pacc[8][4];
#pragma unroll
            for (int i = 0; i < 8; ++i)
#pragma unroll
                for (int j = 0; j < 4; ++j) pacc[i][j] = 0.f;

#pragma unroll
            for (int ks = 0; ks < 2; ++ks) {
                const u32 koff = (u32)((h * 32 + ks * 16) * 2);
                u32 ah[4], al[4];
                ldsm_x4(ah, aHi + koff);
                ldsm_x4(al, aLo + koff);
#pragma unroll
                for (int np = 0; np < 4; ++np) {
                    const u32 boff = koff + (u32)(np * 16 * PITCH * 2);
                    u32 bh[4], bl[4];
                    ldsm_x4(bh, bHiG + boff);
                    ldsm_x4(bl, bLoG + boff);
                    mma16816(pacc[2 * np],     ah, bh[0], bh[1]);
                    mma16816(pacc[2 * np],     ah, bl[0], bl[1]);
                    mma16816(pacc[2 * np],     al, bh[0], bh[1]);
                    mma16816(pacc[2 * np + 1], ah, bh[2], bh[3]);
                    mma16816(pacc[2 * np + 1], ah, bl[2], bl[3]);
                    mma16816(pacc[2 * np + 1], al, bh[2], bh[3]);
                }
            }
            float z0 = zs[(arow + g) * 4 + h];
            float z1 = zs[(arow + g + 8) * 4 + h];
#pragma unroll
            for (int nt = 0; nt < 8; ++nt) {
                acc[nt][0] += z0 * pacc[nt][0];
                acc[nt][1] += z0 * pacc[nt][1];
                acc[nt][2] += z1 * pacc[nt][2];
                acc[nt][3] += z1 * pacc[nt][3];
            }
        }

#pragma unroll
        for (int nt = 0; nt < 8; ++nt) {
            int col = ncol0 + nt * 8 + 2 * c;
            float2 bb = *(const float2*)(bo_s + col);
            float2 r0, r1;
            r0.x = acc[nt][0] + bb.x; r0.y = acc[nt][1] + bb.y;
            r1.x = acc[nt][2] + bb.x; r1.y = acc[nt][3] + bb.y;
            size_t ra = row0 + arow + g;
            *(float2*)(out + ra * EDIM + col)       = r0;
            *(float2*)(out + (ra + 8) * EDIM + col) = r1;
        }
    }
}

// ---------------------------------------------------------------------------
extern "C" void kernel_launch(void* const* d_in, const int* in_sizes, int n_in,
                              void* d_out, int out_size)
{
    const float* x  = (const float*)d_in[0];
    const float* Wq = (const float*)d_in[1];
    const float* bq = (const float*)d_in[2];
    const float* Wk = (const float*)d_in[3];
    const float* bk = (const float*)d_in[4];
    const float* Wv = (const float*)d_in[5];
    const float* bv = (const float*)d_in[6];
    const float* Wo = (const float*)d_in[7];
    const float* bo = (const float*)d_in[8];
    float* out = (float*)d_out;

    cudaFuncSetAttribute(kv_kernel, cudaFuncAttributeMaxDynamicSharedMemorySize, SMEM_KV);
    cudaFuncSetAttribute(out_kernel, cudaFuncAttributeMaxDynamicSharedMemorySize, SMEM_OUT);

    wprep_kernel<<<3, 256>>>(Wq, Wk, Wv);
    kv_kernel<<<NCTA, 512, SMEM_KV>>>(x, bk, bv);
    fold_kernel<<<NBR * HEADS, 256>>>(Wo);
    out_kernel<<<NCTA, 512, SMEM_OUT>>>(bq, bo, out);
}

// round 13
// speedup vs baseline: 1.3456x; 1.2011x over previous
#include <cuda_runtime.h>
#include <cuda_fp16.h>
#include <cstdint>

#define BATCH 2
#define RDIM  64
#define CDIM  2048
#define EDIM  128
#define HEADS 4
#define DHEAD 32
#define NROWS (BATCH*RDIM*CDIM)      // 262144
#define NBR   (BATCH*RDIM)           // 128
#define NCTA  (NROWS/128)            // 2048
#define PART_STRIDE 4224

#define PITCH 136                     // fp16 elements per row

typedef unsigned int u32;

// Scratch (device globals)
__device__ float g_ksum[(size_t)NBR * HEADS * DHEAD];
__device__ __align__(16) float g_part[(size_t)NCTA * PART_STRIDE];
__device__ __align__(16) __half g_G[NBR][2][128 * PITCH];     // hi/lo fp16
__device__ __align__(16) __half g_wt[3][2][128 * PITCH];      // hi/lo fp16
__device__ __align__(16) __half g_xs[NCTA][128 * PITCH];      // x hi only

__device__ __forceinline__ float elu1(float x) {
    return x > 0.f ? x + 1.f : expf(x);
}

// f16 mma m16n8k16
__device__ __forceinline__ void mma16816(float* d, const u32* a, u32 b0, u32 b1) {
    asm volatile(
        "mma.sync.aligned.m16n8k16.row.col.f32.f16.f16.f32 "
        "{%0,%1,%2,%3}, {%4,%5,%6,%7}, {%8,%9}, {%0,%1,%2,%3};"
        : "+f"(d[0]), "+f"(d[1]), "+f"(d[2]), "+f"(d[3])
        : "r"(a[0]), "r"(a[1]), "r"(a[2]), "r"(a[3]), "r"(b0), "r"(b1));
}

__device__ __forceinline__ void ldsm_x4(u32* r, u32 addr) {
    asm volatile("ldmatrix.sync.aligned.m8n8.x4.shared.b16 {%0,%1,%2,%3}, [%4];"
        : "=r"(r[0]), "=r"(r[1]), "=r"(r[2]), "=r"(r[3]) : "r"(addr));
}

__device__ __forceinline__ void ldsm_x4_t(u32* r, u32 addr) {
    asm volatile("ldmatrix.sync.aligned.m8n8.x4.trans.shared.b16 {%0,%1,%2,%3}, [%4];"
        : "=r"(r[0]), "=r"(r[1]), "=r"(r[2]), "=r"(r[3]) : "r"(addr));
}

__device__ __forceinline__ uint32_t smem_u32(const void* p) {
    uint32_t a;
    asm("{ .reg .u64 t; cvta.to.shared.u64 t, %1; cvt.u32.u64 %0, t; }" : "=r"(a) : "l"(p));
    return a;
}

__device__ __forceinline__ void cp_async16(u32 saddr, const void* gptr) {
    asm volatile("cp.async.cg.shared.global [%0], [%1], 16;"
        :: "r"(saddr), "l"(gptr));
}
#define CP_COMMIT() asm volatile("cp.async.commit_group;" ::: "memory")
#define CP_WAIT0()  asm volatile("cp.async.wait_group 0;" ::: "memory")

__device__ __forceinline__ u32 pack_hf2(float x, float y) {
    __half2 p = __floats2half2_rn(x, y);
    return *(u32*)&p;
}
__device__ __forceinline__ float hf_lo(u32 u) {
    return __half2float(*(__half*)&u);
}
__device__ __forceinline__ float hf_hi(u32 u) {
    return __half2float(((__half*)&u)[1]);
}

// 2-pass split GEMM: A hi-only, B = Bh + Bl. acc-major order.
__device__ __forceinline__ void gemm2p_ldsm(
    u32 aHi, u32 bHi, u32 bLo, float acc[8][4])
{
#pragma unroll
    for (int k0 = 0; k0 < 128; k0 += 16) {
        const u32 koff = (u32)(k0 * 2);
        u32 ah[4];
        ldsm_x4(ah, aHi + koff);
#pragma unroll
        for (int np = 0; np < 4; ++np) {
            const u32 boff = koff + (u32)(np * 16 * PITCH * 2);
            u32 bh[4], bl[4];
            ldsm_x4(bh, bHi + boff);
            ldsm_x4(bl, bLo + boff);
            mma16816(acc[2 * np],     ah, bh[0], bh[1]);
            mma16816(acc[2 * np],     ah, bl[0], bl[1]);
            mma16816(acc[2 * np + 1], ah, bh[2], bh[3]);
            mma16816(acc[2 * np + 1], ah, bl[2], bl[3]);
        }
    }
}

__device__ __forceinline__ u32 a_base(u32 sb, int region, int arow, int lane) {
    return sb + (u32)region +
        (u32)(((arow + (lane & 15)) * PITCH + ((lane & 16) ? 8 : 0)) * 2);
}
__device__ __forceinline__ u32 b_base(u32 sb, int region, int ncol0, int lane) {
    return sb + (u32)region +
        (u32)(((ncol0 + (lane & 7) + ((lane & 16) ? 8 : 0)) * PITCH +
               ((lane & 8) ? 8 : 0)) * 2);
}

// ---------------------------------------------------------------------------
// wprep: W[k][n] fp32 -> Wt[n][k] fp16 hi/lo. grid=3 (Wq, Wk, Wv).
// ---------------------------------------------------------------------------
__global__ __launch_bounds__(256) void wprep_kernel(
    const float* __restrict__ Wq, const float* __restrict__ Wk,
    const float* __restrict__ Wv)
{
    const float* Wl[3] = {Wq, Wk, Wv};
    const float* W = Wl[blockIdx.x];
    __half* hi = g_wt[blockIdx.x][0];
    __half* lo = g_wt[blockIdx.x][1];
    for (int i = threadIdx.x; i < 128 * 128; i += 256) {
        int k = i >> 7, n = i & 127;
        float v = W[i];
        __half h = __float2half_rn(v);
        __half l = __float2half_rn(v - __half2float(h));
        hi[n * PITCH + k] = h;
        lo[n * PITCH + k] = l;
    }
}

// ---------------------------------------------------------------------------
// KV + fused per-CTA KtV partial + x-hi export. 128-row tiles, 512 threads.
// QA_HI: x hi.  QB: Wk hi/lo -> k hi (lo dead).  KS: Wv hi/lo -> v hi/lo.
// ---------------------------------------------------------------------------
#define QA_HI 0
#define QB_HI 34816
#define QB_LO 69632
#define KS_HI 104448
#define KS_LO 139264
#define QBIAS 174080            // 2*128 f
#define QKSUM 175104            // float[8][128]
#define SMEM_KV (QKSUM + 8 * 128 * 4)

__global__ __launch_bounds__(512, 1) void kv_kernel(
    const float* __restrict__ x,
    const float* __restrict__ bk, const float* __restrict__ bv)
{
    extern __shared__ char smem[];
    const u32 sb = smem_u32(smem);
    const int tid = threadIdx.x;
    const int wid = tid >> 5;
    const int lane = tid & 31;
    const int g = lane >> 2, c = lane & 3;
    const size_t row0 = (size_t)blockIdx.x * 128;

    float* sbias = (float*)(smem + QBIAS);
    float* sksum = (float*)(smem + QKSUM);
    if (tid < 128) {
        sbias[tid]       = bk[tid];
        sbias[128 + tid] = bv[tid];
    }

    // prefetch Wk -> QB, Wv -> KS
    {
        const uint4* wkh = (const uint4*)g_wt[1][0];
        const uint4* wkl = (const uint4*)g_wt[1][1];
        const uint4* wvh = (const uint4*)g_wt[2][0];
        const uint4* wvl = (const uint4*)g_wt[2][1];
#pragma unroll
        for (int i = 0; i < 5; ++i) {
            int idx = tid + i * 512;
            if (idx < 2176) {
                cp_async16(sb + QB_HI + idx * 16, wkh + idx);
                cp_async16(sb + QB_LO + idx * 16, wkl + idx);
                cp_async16(sb + KS_HI + idx * 16, wvh + idx);
                cp_async16(sb + KS_LO + idx * 16, wvl + idx);
            }
        }
        CP_COMMIT();
    }

    // load x tile, fp16-hi into QA + export to g_xs
    {
        const float4* xg = reinterpret_cast<const float4*>(x + row0 * EDIM);
        char* xs_hi = (char*)g_xs[blockIdx.x];
#pragma unroll
        for (int i = 0; i < 8; ++i) {
            int idx = tid + i * 512;
            int row = idx >> 5;
            int c4  = (idx & 31) << 2;
            float4 v = xg[idx];
            uint2 hh = make_uint2(pack_hf2(v.x, v.y), pack_hf2(v.z, v.w));
            int off = (row * PITCH + c4) * 2;
            *(uint2*)(smem + QA_HI + off) = hh;
            *(uint2*)(xs_hi + off) = hh;    // fire-and-forget export
        }
    }
    CP_WAIT0();
    __syncthreads();

    const int arow = (wid & 7) * 16;
    const int ncol0 = (wid >> 3) * 64;
    const int aw = wid & 7;

    const u32 aHi = a_base(sb, QA_HI, arow, lane);
    const u32 bHiK = b_base(sb, QB_HI, ncol0, lane);
    const u32 bLoK = b_base(sb, QB_LO, ncol0, lane);
    const u32 bHiV = b_base(sb, KS_HI, ncol0, lane);
    const u32 bLoV = b_base(sb, KS_LO, ncol0, lane);

    // ---- k projection ----
    {
        float acc[8][4];
#pragma unroll
        for (int i = 0; i < 8; ++i)
#pragma unroll
            for (int j = 0; j < 4; ++j) acc[i][j] = 0.f;

        gemm2p_ldsm(aHi, bHiK, bLoK, acc);
        __syncthreads();   // all Wk reads done -> QB reusable

        // epilogue: bias + elu, k-hi -> QB_HI; ksum partials
#pragma unroll
        for (int nt = 0; nt < 8; ++nt) {
            int col = ncol0 + nt * 8 + 2 * c;
            float2 bb = *(const float2*)(sbias + col);
            float k0x = elu1(acc[nt][0] + bb.x), k0y = elu1(acc[nt][1] + bb.y);
            float k1x = elu1(acc[nt][2] + bb.x), k1y = elu1(acc[nt][3] + bb.y);
            int o0 = ((arow + g) * PITCH + col) * 2;
            int o1 = ((arow + g + 8) * PITCH + col) * 2;
            *(u32*)(smem + QB_HI + o0) = pack_hf2(k0x, k0y);
            *(u32*)(smem + QB_HI + o1) = pack_hf2(k1x, k1y);
            float s0 = k0x + k1x;
            float s1 = k0y + k1y;
            s0 += __shfl_xor_sync(0xffffffffu, s0, 16);
            s0 += __shfl_xor_sync(0xffffffffu, s0, 8);
            s0 += __shfl_xor_sync(0xffffffffu, s0, 4);
            s1 += __shfl_xor_sync(0xffffffffu, s1, 16);
            s1 += __shfl_xor_sync(0xffffffffu, s1, 8);
            s1 += __shfl_xor_sync(0xffffffffu, s1, 4);
            if (lane < 4) {
                sksum[aw * 128 + col]     = s0;
                sksum[aw * 128 + col + 1] = s1;
            }
        }
    }

    // ---- v projection (Wv resident in KS) ----
    {
        float acc[8][4];
#pragma unroll
        for (int i = 0; i < 8; ++i)
#pragma unroll
            for (int j = 0; j < 4; ++j) acc[i][j] = 0.f;

        gemm2p_ldsm(aHi, bHiV, bLoV, acc);

        const float* bias = sbias + 128;
#pragma unroll
        for (int nt = 0; nt < 8; ++nt) {
            int col = ncol0 + nt * 8 + 2 * c;
            float2 bb = *(const float2*)(bias + col);
            acc[nt][0] += bb.x; acc[nt][1] += bb.y;
            acc[nt][2] += bb.x; acc[nt][3] += bb.y;
        }
        __syncthreads();   // all Wv reads done -> KS reusable
#pragma unroll
        for (int nt = 0; nt < 8; ++nt) {
            int col = ncol0 + nt * 8 + 2 * c;
            u32 h0 = pack_hf2(acc[nt][0], acc[nt][1]);
            u32 h1 = pack_hf2(acc[nt][2], acc[nt][3]);
            u32 l0 = pack_hf2(acc[nt][0] - hf_lo(h0), acc[nt][1] - hf_hi(h0));
            u32 l1 = pack_hf2(acc[nt][2] - hf_lo(h1), acc[nt][3] - hf_hi(h1));
            int o0 = ((arow + g) * PITCH + col) * 2;
            int o1 = ((arow + g + 8) * PITCH + col) * 2;
            *(u32*)(smem + KS_HI + o0) = h0;
            *(u32*)(smem + KS_LO + o0) = l0;
            *(u32*)(smem + KS_HI + o1) = h1;
            *(u32*)(smem + KS_LO + o1) = l1;
        }
    }
    __syncthreads();   // k-hi + v-split + sksum complete

    if (tid < 128) {
        float s = 0.f;
#pragma unroll
        for (int i = 0; i < 8; ++i) s += sksum[i * 128 + tid];
        g_part[(size_t)blockIdx.x * PART_STRIDE + 4096 + tid] = s;
    }

    // ---- KtV partial phase: A = k-hi (QB_HI), B = v hi/lo (KS) ----
    {
        const int h  = wid & 3;
        const int mt = (wid >> 2) & 1;
        const int np = wid >> 3;
        const int d0 = h * 32 + mt * 16;
        const int e0 = h * 32 + np * 16;

        const u32 a_roff = (u32)(((lane & 7) + ((lane & 16) ? 8 : 0)) * (PITCH * 2));
        const u32 a_coff = (u32)((d0 + ((lane & 8) ? 8 : 0)) * 2);
        const u32 b_roff = (u32)(((lane & 7) + ((lane & 8) ? 8 : 0)) * (PITCH * 2));
        const u32 b_coff = (u32)((e0 + ((lane & 16) ? 8 : 0)) * 2);
        const u32 a_hi = sb + QB_HI + a_roff + a_coff;
        const u32 b_hi = sb + KS_HI + b_roff + b_coff;
        const u32 b_lo = sb + KS_LO + b_roff + b_coff;

        float acc[2][4];
#pragma unroll
        for (int i = 0; i < 2; ++i)
#pragma unroll
            for (int j = 0; j < 4; ++j) acc[i][j] = 0.f;

#pragma unroll
        for (int c0 = 0; c0 < 128; c0 += 16) {
            u32 off = (u32)(c0 * (PITCH * 2));
            u32 ah[4], bh[4], bl[4];
            ldsm_x4_t(ah, a_hi + off);
            ldsm_x4_t(bh, b_hi + off);
            ldsm_x4_t(bl, b_lo + off);
            mma16816(acc[0], ah, bh[0], bh[1]);
            mma16816(acc[1], ah, bh[2], bh[3]);
            mma16816(acc[0], ah, bl[0], bl[1]);
            mma16816(acc[1], ah, bl[2], bl[3]);
        }

        float* dst = g_part + (size_t)blockIdx.x * PART_STRIDE + h * 1024;
#pragma unroll
        for (int nt = 0; nt < 2; ++nt) {
            int d_lo = mt * 16 + g;
            int e_lo = np * 16 + nt * 8 + 2 * c;
            *(float2*)&dst[d_lo * 32 + e_lo]       = make_float2(acc[nt][0], acc[nt][1]);
            *(float2*)&dst[(d_lo + 8) * 32 + e_lo] = make_float2(acc[nt][2], acc[nt][3]);
        }
    }
}

// ---------------------------------------------------------------------------
// fold: per (br,h): reduce 16 CTA partials -> KtV; ksum (h==0);
//       G[d][n] -> fp16 hi/lo [n][k] layout.
// ---------------------------------------------------------------------------
__global__ __launch_bounds__(256) void fold_kernel(const float* __restrict__ Wo)
{
    __shared__ float ktv_s[1024];   // [e][d]
    __shared__ float ws[4096];      // Wo slice [32][128]

    const int tid = threadIdx.x;
    const int br  = blockIdx.x >> 2;
    const int h   = blockIdx.x & 3;
    const float* base = g_part + (size_t)br * 16 * PART_STRIDE;

    {
        float v0 = 0.f, v1 = 0.f, v2 = 0.f, v3 = 0.f;
#pragma unroll 4
        for (int i = 0; i < 16; ++i) {
            float4 p = *(const float4*)(base + (size_t)i * PART_STRIDE + h * 1024 + tid * 4);
            v0 += p.x; v1 += p.y; v2 += p.z; v3 += p.w;
        }
        int d = tid >> 3, e0 = (tid & 7) * 4;
        ktv_s[(e0 + 0) * 32 + d] = v0;
        ktv_s[(e0 + 1) * 32 + d] = v1;
        ktv_s[(e0 + 2) * 32 + d] = v2;
        ktv_s[(e0 + 3) * 32 + d] = v3;
    }

    if (h == 0 && tid < 128) {
        float s = 0.f;
#pragma unroll 4
        for (int i = 0; i < 16; ++i)
            s += base[(size_t)i * PART_STRIDE + 4096 + tid];
        g_ksum[(size_t)br * 128 + tid] = s;
    }

    {
        const float4* wg = reinterpret_cast<const float4*>(Wo + h * 4096);
#pragma unroll
        for (int i = 0; i < 4; ++i)
            reinterpret_cast<float4*>(ws)[tid + i * 256] = wg[tid + i * 256];
    }
    __syncthreads();

    {
        const int n  = tid >> 1;
        const int d0 = (tid & 1) * 16;
        float acc[16];
#pragma unroll
        for (int j = 0; j < 16; ++j) acc[j] = 0.f;
#pragma unroll 4
        for (int dp = 0; dp < 32; ++dp) {
            float w = ws[dp * 128 + n];
            const float4* kp = (const float4*)(ktv_s + dp * 32 + d0);
            float4 k0 = kp[0], k1 = kp[1], k2 = kp[2], k3 = kp[3];
            acc[0]  += w * k0.x; acc[1]  += w * k0.y; acc[2]  += w * k0.z; acc[3]  += w * k0.w;
            acc[4]  += w * k1.x; acc[5]  += w * k1.y; acc[6]  += w * k1.z; acc[7]  += w * k1.w;
            acc[8]  += w * k2.x; acc[9]  += w * k2.y; acc[10] += w * k2.z; acc[11] += w * k2.w;
            acc[12] += w * k3.x; acc[13] += w * k3.y; acc[14] += w * k3.z; acc[15] += w * k3.w;
        }
        __half hbuf[16], lbuf[16];
#pragma unroll
        for (int j = 0; j < 16; ++j) {
            __half hv = __float2half_rn(acc[j]);
            hbuf[j] = hv;
            lbuf[j] = __float2half_rn(acc[j] - __half2float(hv));
        }
        int eo = n * PITCH + h * 32 + d0;
        uint4* dh = (uint4*)&g_G[br][0][eo];
        uint4* dl = (uint4*)&g_G[br][1][eo];
        dh[0] = ((uint4*)hbuf)[0]; dh[1] = ((uint4*)hbuf)[1];
        dl[0] = ((uint4*)lbuf)[0]; dl[1] = ((uint4*)lbuf)[1];
    }
}

// ---------------------------------------------------------------------------
// out: q = elu(xs@Wq+bq); z folded into q epilogue; out = sum_h z_h*(q_h@G_h)+bo.
// OA_HI: xs -> q hi.  OB: Wq hi/lo.  OG: G hi/lo.  All cp.async.
// ---------------------------------------------------------------------------
#define OA_HI 0
#define OB_HI 34816
#define OB_LO 69632
#define OG_HI 104448
#define OG_LO 139264
#define OKS   174080            // ksum 128f
#define OZ    174592            // z 512f
#define OBQ   176640            // bq 128f
#define OBO   177152            // bo 128f
#define SMEM_OUT (OBO + 512)

__global__ __launch_bounds__(512, 1) void out_kernel(
    const float* __restrict__ bq,
    const float* __restrict__ bo, float* __restrict__ out)
{
    extern __shared__ char smem[];
    const u32 sb = smem_u32(smem);
    const int tid = threadIdx.x;
    const int wid = tid >> 5;
    const int lane = tid & 31;
    const int g = lane >> 2, c = lane & 3;
    const size_t row0 = (size_t)blockIdx.x * 128;
    const int br = blockIdx.x >> 4;

    float* ks_s = (float*)(smem + OKS);
    float* zs   = (float*)(smem + OZ);
    float* bq_s = (float*)(smem + OBQ);
    float* bo_s = (float*)(smem + OBO);

    // prefetch xs -> OA_HI, Wq -> OB, G -> OG
    {
        const uint4* xsh = (const uint4*)g_xs[blockIdx.x];
        const uint4* wqh = (const uint4*)g_wt[0][0];
        const uint4* wql = (const uint4*)g_wt[0][1];
        const uint4* gh  = (const uint4*)g_G[br][0];
        const uint4* gl  = (const uint4*)g_G[br][1];
#pragma unroll
        for (int i = 0; i < 5; ++i) {
            int idx = tid + i * 512;
            if (idx < 2176) {
                cp_async16(sb + OA_HI + idx * 16, xsh + idx);
                cp_async16(sb + OB_HI + idx * 16, wqh + idx);
                cp_async16(sb + OB_LO + idx * 16, wql + idx);
                cp_async16(sb + OG_HI + idx * 16, gh + idx);
                cp_async16(sb + OG_LO + idx * 16, gl + idx);
            }
        }
        CP_COMMIT();
    }

    if (tid < 128) ks_s[tid] = g_ksum[(size_t)br * 128 + tid];
    else if (tid < 256) bq_s[tid - 128] = bq[tid - 128];
    else if (tid < 384) bo_s[tid - 256] = bo[tid - 256];

    CP_WAIT0();
    __syncthreads();

    const int arow = (wid & 7) * 16;
    const int ncol0 = (wid >> 3) * 64;
    const u32 aHi = a_base(sb, OA_HI, arow, lane);
    const u32 bHiW = b_base(sb, OB_HI, ncol0, lane);
    const u32 bLoW = b_base(sb, OB_LO, ncol0, lane);
    const u32 bHiG = b_base(sb, OG_HI, ncol0, lane);
    const u32 bLoG = b_base(sb, OG_LO, ncol0, lane);

    // q = xs @ Wq (2-pass)
    float qa[8][4];
#pragma unroll
    for (int i = 0; i < 8; ++i)
#pragma unroll
        for (int j = 0; j < 4; ++j) qa[i][j] = 0.f;
    gemm2p_ldsm(aHi, bHiW, bLoW, qa);

    __syncthreads();   // all xs reads (OA) done

    // epilogue: bias + elu, q-hi into OA, fold z-dot accumulation
    {
        float d00 = 0.f, d01 = 0.f, d10 = 0.f, d11 = 0.f;
#pragma unroll
        for (int nt = 0; nt < 8; ++nt) {
            int col = ncol0 + nt * 8 + 2 * c;
            float2 bb = *(const float2*)(bq_s + col);
            float q0x = elu1(qa[nt][0] + bb.x), q0y = elu1(qa[nt][1] + bb.y);
            float q1x = elu1(qa[nt][2] + bb.x), q1y = elu1(qa[nt][3] + bb.y);
            float2 kk = *(const float2*)(ks_s + col);
            float t0 = q0x * kk.x + q0y * kk.y;
            float t1 = q1x * kk.x + q1y * kk.y;
            if (nt < 4) { d00 += t0; d10 += t1; }
            else        { d01 += t0; d11 += t1; }
            int o0 = ((arow + g) * PITCH + col) * 2;
            int o1 = ((arow + g + 8) * PITCH + col) * 2;
            *(u32*)(smem + OA_HI + o0) = pack_hf2(q0x, q0y);
            *(u32*)(smem + OA_HI + o1) = pack_hf2(q1x, q1y);
        }
        d00 += __shfl_xor_sync(0xffffffffu, d00, 1);
        d00 += __shfl_xor_sync(0xffffffffu, d00, 2);
        d01 += __shfl_xor_sync(0xffffffffu, d01, 1);
        d01 += __shfl_xor_sync(0xffffffffu, d01, 2);
        d10 += __shfl_xor_sync(0xffffffffu, d10, 1);
        d10 += __shfl_xor_sync(0xffffffffu, d10, 2);
        d11 += __shfl_xor_sync(0xffffffffu, d11, 1);
        d11 += __shfl_xor_sync(0xffffffffu, d11, 2);
        if (c == 0) {
            int h0 = ncol0 >> 5;   // 0 or 2
            zs[(arow + g) * 4 + h0]         = d00;
            zs[(arow + g) * 4 + h0 + 1]     = d01;
            zs[(arow + g + 8) * 4 + h0]     = d10;
            zs[(arow + g + 8) * 4 + h0 + 1] = d11;
        }
    }
    __syncthreads();   // q-hi + raw dots visible

    zs[tid] = 1.f / (zs[tid] + 1e-6f);
    __syncthreads();

    // out = sum_h z_h * (q_h @ G_h) + bo  (2-pass per head)
    {
        float acc[8][4];
#pragma unroll
        for (int i = 0; i < 8; ++i)
#pragma unroll
            for (int j = 0; j < 4; ++j) acc[i][j] = 0.f;

#pragma unroll
        for (int h = 0; h < 4; ++h) {
            float pacc[8][4];
#pragma unroll
            for (int i = 0; i < 8; ++i)
#pragma unroll
                for (int j = 0; j < 4; ++j) pacc[i][j] = 0.f;

#pragma unroll
            for (int ks = 0; ks < 2; ++ks) {
                const u32 koff = (u32)((h * 32 + ks * 16) * 2);
                u32 ah[4];
                ldsm_x4(ah, aHi + koff);
#pragma unroll
                for (int np = 0; np < 4; ++np) {
                    const u32 boff = koff + (u32)(np * 16 * PITCH * 2);
                    u32 bh[4], bl[4];
                    ldsm_x4(bh, bHiG + boff);
                    ldsm_x4(bl, bLoG + boff);
                    mma16816(pacc[2 * np],     ah, bh[0], bh[1]);
                    mma16816(pacc[2 * np],     ah, bl[0], bl[1]);
                    mma16816(pacc[2 * np + 1], ah, bh[2], bh[3]);
                    mma16816(pacc[2 * np + 1], ah, bl[2], bl[3]);
                }
            }
            float z0 = zs[(arow + g) * 4 + h];
            float z1 = zs[(arow + g + 8) * 4 + h];
#pragma unroll
            for (int nt = 0; nt < 8; ++nt) {
                acc[nt][0] += z0 * pacc[nt][0];
                acc[nt][1] += z0 * pacc[nt][1];
                acc[nt][2] += z1 * pacc[nt][2];
                acc[nt][3] += z1 * pacc[nt][3];
            }
        }

#pragma unroll
        for (int nt = 0; nt < 8; ++nt) {
            int col = ncol0 + nt * 8 + 2 * c;
            float2 bb = *(const float2*)(bo_s + col);
            float2 r0, r1;
            r0.x = acc[nt][0] + bb.x; r0.y = acc[nt][1] + bb.y;
            r1.x = acc[nt][2] + bb.x; r1.y = acc[nt][3] + bb.y;
            size_t ra = row0 + arow + g;
            *(float2*)(out + ra * EDIM + col)       = r0;
            *(float2*)(out + (ra + 8) * EDIM + col) = r1;
        }
    }
}

// ---------------------------------------------------------------------------
extern "C" void kernel_launch(void* const* d_in, const int* in_sizes, int n_in,
                              void* d_out, int out_size)
{
    const float* x  = (const float*)d_in[0];
    const float* Wq = (const float*)d_in[1];
    const float* bq = (const float*)d_in[2];
    const float* Wk = (const float*)d_in[3];
    const float* bk = (const float*)d_in[4];
    const float* Wv = (const float*)d_in[5];
    const float* bv = (const float*)d_in[6];
    const float* Wo = (const float*)d_in[7];
    const float* bo = (const float*)d_in[8];
    float* out = (float*)d_out;

    cudaFuncSetAttribute(kv_kernel, cudaFuncAttributeMaxDynamicSharedMemorySize, SMEM_KV);
    cudaFuncSetAttribute(out_kernel, cudaFuncAttributeMaxDynamicSharedMemorySize, SMEM_OUT);

    wprep_kernel<<<3, 256>>>(Wq, Wk, Wv);
    kv_kernel<<<NCTA, 512, SMEM_KV>>>(x, bk, bv);
    fold_kernel<<<NBR * HEADS, 256>>>(Wo);
    out_kernel<<<NCTA, 512, SMEM_OUT>>>(bq, bo, out);
}

// round 14
// speedup vs baseline: 1.7618x; 1.3093x over previous
#include <cuda_runtime.h>
#include <cuda_fp16.h>
#include <cstdint>

#define BATCH 2
#define RDIM  64
#define CDIM  2048
#define EDIM  128
#define HEADS 4
#define DHEAD 32
#define NROWS (BATCH*RDIM*CDIM)      // 262144
#define NBR   (BATCH*RDIM)           // 128
#define NCTA  (NROWS/128)            // 2048
#define PART_STRIDE 4224

#define PITCH 136                     // fp16 elements per row

typedef unsigned int u32;

// Scratch (device globals)
__device__ float g_ksum[(size_t)NBR * HEADS * DHEAD];
__device__ __align__(16) float g_part[(size_t)NCTA * PART_STRIDE];
__device__ __align__(16) __half g_G[NBR][128 * PITCH];        // fp16
__device__ __align__(16) __half g_wt[3][128 * PITCH];         // fp16
__device__ __align__(16) __half g_xs[NCTA][128 * PITCH];      // x fp16

__device__ __forceinline__ float elu1(float x) {
    return x > 0.f ? x + 1.f : expf(x);
}

__device__ __forceinline__ void mma16816(float* d, const u32* a, u32 b0, u32 b1) {
    asm volatile(
        "mma.sync.aligned.m16n8k16.row.col.f32.f16.f16.f32 "
        "{%0,%1,%2,%3}, {%4,%5,%6,%7}, {%8,%9}, {%0,%1,%2,%3};"
        : "+f"(d[0]), "+f"(d[1]), "+f"(d[2]), "+f"(d[3])
        : "r"(a[0]), "r"(a[1]), "r"(a[2]), "r"(a[3]), "r"(b0), "r"(b1));
}

__device__ __forceinline__ void ldsm_x4(u32* r, u32 addr) {
    asm volatile("ldmatrix.sync.aligned.m8n8.x4.shared.b16 {%0,%1,%2,%3}, [%4];"
        : "=r"(r[0]), "=r"(r[1]), "=r"(r[2]), "=r"(r[3]) : "r"(addr));
}

__device__ __forceinline__ void ldsm_x4_t(u32* r, u32 addr) {
    asm volatile("ldmatrix.sync.aligned.m8n8.x4.trans.shared.b16 {%0,%1,%2,%3}, [%4];"
        : "=r"(r[0]), "=r"(r[1]), "=r"(r[2]), "=r"(r[3]) : "r"(addr));
}

__device__ __forceinline__ uint32_t smem_u32(const void* p) {
    uint32_t a;
    asm("{ .reg .u64 t; cvta.to.shared.u64 t, %1; cvt.u32.u64 %0, t; }" : "=r"(a) : "l"(p));
    return a;
}

__device__ __forceinline__ void cp_async16(u32 saddr, const void* gptr) {
    asm volatile("cp.async.cg.shared.global [%0], [%1], 16;"
        :: "r"(saddr), "l"(gptr));
}
#define CP_COMMIT() asm volatile("cp.async.commit_group;" ::: "memory")
#define CP_WAIT0()  asm volatile("cp.async.wait_group 0;" ::: "memory")

__device__ __forceinline__ u32 pack_hf2(float x, float y) {
    __half2 p = __floats2half2_rn(x, y);
    return *(u32*)&p;
}

// single-pass fp16 GEMM, 8 n-tiles, K=128
__device__ __forceinline__ void gemm1p_ldsm(u32 aHi, u32 bHi, float acc[8][4])
{
#pragma unroll
    for (int k0 = 0; k0 < 128; k0 += 16) {
        const u32 koff = (u32)(k0 * 2);
        u32 ah[4];
        ldsm_x4(ah, aHi + koff);
#pragma unroll
        for (int np = 0; np < 4; ++np) {
            u32 bh[4];
            ldsm_x4(bh, bHi + koff + (u32)(np * 16 * PITCH * 2));
            mma16816(acc[2 * np],     ah, bh[0], bh[1]);
            mma16816(acc[2 * np + 1], ah, bh[2], bh[3]);
        }
    }
}

__device__ __forceinline__ u32 a_base(u32 sb, int region, int arow, int lane) {
    return sb + (u32)region +
        (u32)(((arow + (lane & 15)) * PITCH + ((lane & 16) ? 8 : 0)) * 2);
}
__device__ __forceinline__ u32 b_base(u32 sb, int region, int ncol0, int lane) {
    return sb + (u32)region +
        (u32)(((ncol0 + (lane & 7) + ((lane & 16) ? 8 : 0)) * PITCH +
               ((lane & 8) ? 8 : 0)) * 2);
}

// ---------------------------------------------------------------------------
// wprep: W[k][n] fp32 -> Wt[n][k] fp16. grid=3 (Wq, Wk, Wv).
// ---------------------------------------------------------------------------
__global__ __launch_bounds__(256) void wprep_kernel(
    const float* __restrict__ Wq, const float* __restrict__ Wk,
    const float* __restrict__ Wv)
{
    const float* Wl[3] = {Wq, Wk, Wv};
    const float* W = Wl[blockIdx.x];
    __half* hi = g_wt[blockIdx.x];
    for (int i = threadIdx.x; i < 128 * 128; i += 256) {
        int k = i >> 7, n = i & 127;
        hi[n * PITCH + k] = __float2half_rn(W[i]);
    }
}

// ---------------------------------------------------------------------------
// KV + fused per-CTA KtV partial + x export. 128-row tiles, 512 threads.
// QA: x.  QB: Wk -> k.  KS: Wv -> v.
// ---------------------------------------------------------------------------
#define QA_HI 0
#define QB_HI 34816
#define KS_HI 69632
#define QBIAS 104448            // 2*128 f
#define QKSUM 105472            // float[8][128]
#define SMEM_KV (QKSUM + 8 * 128 * 4)

__global__ __launch_bounds__(512, 1) void kv_kernel(
    const float* __restrict__ x,
    const float* __restrict__ bk, const float* __restrict__ bv)
{
    extern __shared__ char smem[];
    const u32 sb = smem_u32(smem);
    const int tid = threadIdx.x;
    const int wid = tid >> 5;
    const int lane = tid & 31;
    const int g = lane >> 2, c = lane & 3;
    const size_t row0 = (size_t)blockIdx.x * 128;

    float* sbias = (float*)(smem + QBIAS);
    float* sksum = (float*)(smem + QKSUM);
    if (tid < 128) {
        sbias[tid]       = bk[tid];
        sbias[128 + tid] = bv[tid];
    }

    // prefetch Wk -> QB, Wv -> KS
    {
        const uint4* wkh = (const uint4*)g_wt[1];
        const uint4* wvh = (const uint4*)g_wt[2];
#pragma unroll
        for (int i = 0; i < 5; ++i) {
            int idx = tid + i * 512;
            if (idx < 2176) {
                cp_async16(sb + QB_HI + idx * 16, wkh + idx);
                cp_async16(sb + KS_HI + idx * 16, wvh + idx);
            }
        }
        CP_COMMIT();
    }

    // load x tile, fp16 into QA + export to g_xs
    {
        const float4* xg = reinterpret_cast<const float4*>(x + row0 * EDIM);
        char* xs_hi = (char*)g_xs[blockIdx.x];
#pragma unroll
        for (int i = 0; i < 8; ++i) {
            int idx = tid + i * 512;
            int row = idx >> 5;
            int c4  = (idx & 31) << 2;
            float4 v = xg[idx];
            uint2 hh = make_uint2(pack_hf2(v.x, v.y), pack_hf2(v.z, v.w));
            int off = (row * PITCH + c4) * 2;
            *(uint2*)(smem + QA_HI + off) = hh;
            *(uint2*)(xs_hi + off) = hh;
        }
    }
    CP_WAIT0();
    __syncthreads();

    const int arow = (wid & 7) * 16;
    const int ncol0 = (wid >> 3) * 64;
    const int aw = wid & 7;

    const u32 aHi = a_base(sb, QA_HI, arow, lane);
    const u32 bHiK = b_base(sb, QB_HI, ncol0, lane);
    const u32 bHiV = b_base(sb, KS_HI, ncol0, lane);

    // ---- k projection ----
    {
        float acc[8][4];
#pragma unroll
        for (int i = 0; i < 8; ++i)
#pragma unroll
            for (int j = 0; j < 4; ++j) acc[i][j] = 0.f;

        gemm1p_ldsm(aHi, bHiK, acc);
        __syncthreads();   // all Wk reads done -> QB reusable

#pragma unroll
        for (int nt = 0; nt < 8; ++nt) {
            int col = ncol0 + nt * 8 + 2 * c;
            float2 bb = *(const float2*)(sbias + col);
            float k0x = elu1(acc[nt][0] + bb.x), k0y = elu1(acc[nt][1] + bb.y);
            float k1x = elu1(acc[nt][2] + bb.x), k1y = elu1(acc[nt][3] + bb.y);
            int o0 = ((arow + g) * PITCH + col) * 2;
            int o1 = ((arow + g + 8) * PITCH + col) * 2;
            *(u32*)(smem + QB_HI + o0) = pack_hf2(k0x, k0y);
            *(u32*)(smem + QB_HI + o1) = pack_hf2(k1x, k1y);
            float s0 = k0x + k1x;
            float s1 = k0y + k1y;
            s0 += __shfl_xor_sync(0xffffffffu, s0, 16);
            s0 += __shfl_xor_sync(0xffffffffu, s0, 8);
            s0 += __shfl_xor_sync(0xffffffffu, s0, 4);
            s1 += __shfl_xor_sync(0xffffffffu, s1, 16);
            s1 += __shfl_xor_sync(0xffffffffu, s1, 8);
            s1 += __shfl_xor_sync(0xffffffffu, s1, 4);
            if (lane < 4) {
                sksum[aw * 128 + col]     = s0;
                sksum[aw * 128 + col + 1] = s1;
            }
        }
    }

    // ---- v projection (Wv resident in KS) ----
    {
        float acc[8][4];
#pragma unroll
        for (int i = 0; i < 8; ++i)
#pragma unroll
            for (int j = 0; j < 4; ++j) acc[i][j] = 0.f;

        gemm1p_ldsm(aHi, bHiV, acc);

        const float* bias = sbias + 128;
#pragma unroll
        for (int nt = 0; nt < 8; ++nt) {
            int col = ncol0 + nt * 8 + 2 * c;
            float2 bb = *(const float2*)(bias + col);
            acc[nt][0] += bb.x; acc[nt][1] += bb.y;
            acc[nt][2] += bb.x; acc[nt][3] += bb.y;
        }
        __syncthreads();   // all Wv reads done -> KS reusable
#pragma unroll
        for (int nt = 0; nt < 8; ++nt) {
            int col = ncol0 + nt * 8 + 2 * c;
            int o0 = ((arow + g) * PITCH + col) * 2;
            int o1 = ((arow + g + 8) * PITCH + col) * 2;
            *(u32*)(smem + KS_HI + o0) = pack_hf2(acc[nt][0], acc[nt][1]);
            *(u32*)(smem + KS_HI + o1) = pack_hf2(acc[nt][2], acc[nt][3]);
        }
    }
    __syncthreads();   // k + v + sksum complete

    if (tid < 128) {
        float s = 0.f;
#pragma unroll
        for (int i = 0; i < 8; ++i) s += sksum[i * 128 + tid];
        g_part[(size_t)blockIdx.x * PART_STRIDE + 4096 + tid] = s;
    }

    // ---- KtV partial phase: A = k (QB), B = v (KS) ----
    {
        const int h  = wid & 3;
        const int mt = (wid >> 2) & 1;
        const int np = wid >> 3;
        const int d0 = h * 32 + mt * 16;
        const int e0 = h * 32 + np * 16;

        const u32 a_roff = (u32)(((lane & 7) + ((lane & 16) ? 8 : 0)) * (PITCH * 2));
        const u32 a_coff = (u32)((d0 + ((lane & 8) ? 8 : 0)) * 2);
        const u32 b_roff = (u32)(((lane & 7) + ((lane & 8) ? 8 : 0)) * (PITCH * 2));
        const u32 b_coff = (u32)((e0 + ((lane & 16) ? 8 : 0)) * 2);
        const u32 a_hi = sb + QB_HI + a_roff + a_coff;
        const u32 b_hi = sb + KS_HI + b_roff + b_coff;

        float acc[2][4];
#pragma unroll
        for (int i = 0; i < 2; ++i)
#pragma unroll
            for (int j = 0; j < 4; ++j) acc[i][j] = 0.f;

#pragma unroll
        for (int c0 = 0; c0 < 128; c0 += 16) {
            u32 off = (u32)(c0 * (PITCH * 2));
            u32 ah[4], bh[4];
            ldsm_x4_t(ah, a_hi + off);
            ldsm_x4_t(bh, b_hi + off);
            mma16816(acc[0], ah, bh[0], bh[1]);
            mma16816(acc[1], ah, bh[2], bh[3]);
        }

        float* dst = g_part + (size_t)blockIdx.x * PART_STRIDE + h * 1024;
#pragma unroll
        for (int nt = 0; nt < 2; ++nt) {
            int d_lo = mt * 16 + g;
            int e_lo = np * 16 + nt * 8 + 2 * c;
            *(float2*)&dst[d_lo * 32 + e_lo]       = make_float2(acc[nt][0], acc[nt][1]);
            *(float2*)&dst[(d_lo + 8) * 32 + e_lo] = make_float2(acc[nt][2], acc[nt][3]);
        }
    }
}

// ---------------------------------------------------------------------------
// fold: reduce 16 partials -> KtV; ksum (h==0); G -> fp16 [n][k].
// ---------------------------------------------------------------------------
__global__ __launch_bounds__(256) void fold_kernel(const float* __restrict__ Wo)
{
    __shared__ float ktv_s[1024];   // [e][d]
    __shared__ float ws[4096];      // Wo slice [32][128]

    const int tid = threadIdx.x;
    const int br  = blockIdx.x >> 2;
    const int h   = blockIdx.x & 3;
    const float* base = g_part + (size_t)br * 16 * PART_STRIDE;

    {
        float v0 = 0.f, v1 = 0.f, v2 = 0.f, v3 = 0.f;
#pragma unroll 4
        for (int i = 0; i < 16; ++i) {
            float4 p = *(const float4*)(base + (size_t)i * PART_STRIDE + h * 1024 + tid * 4);
            v0 += p.x; v1 += p.y; v2 += p.z; v3 += p.w;
        }
        int d = tid >> 3, e0 = (tid & 7) * 4;
        ktv_s[(e0 + 0) * 32 + d] = v0;
        ktv_s[(e0 + 1) * 32 + d] = v1;
        ktv_s[(e0 + 2) * 32 + d] = v2;
        ktv_s[(e0 + 3) * 32 + d] = v3;
    }

    if (h == 0 && tid < 128) {
        float s = 0.f;
#pragma unroll 4
        for (int i = 0; i < 16; ++i)
            s += base[(size_t)i * PART_STRIDE + 4096 + tid];
        g_ksum[(size_t)br * 128 + tid] = s;
    }

    {
        const float4* wg = reinterpret_cast<const float4*>(Wo + h * 4096);
#pragma unroll
        for (int i = 0; i < 4; ++i)
            reinterpret_cast<float4*>(ws)[tid + i * 256] = wg[tid + i * 256];
    }
    __syncthreads();

    {
        const int n  = tid >> 1;
        const int d0 = (tid & 1) * 16;
        float acc[16];
#pragma unroll
        for (int j = 0; j < 16; ++j) acc[j] = 0.f;
#pragma unroll 4
        for (int dp = 0; dp < 32; ++dp) {
            float w = ws[dp * 128 + n];
            const float4* kp = (const float4*)(ktv_s + dp * 32 + d0);
            float4 k0 = kp[0], k1 = kp[1], k2 = kp[2], k3 = kp[3];
            acc[0]  += w * k0.x; acc[1]  += w * k0.y; acc[2]  += w * k0.z; acc[3]  += w * k0.w;
            acc[4]  += w * k1.x; acc[5]  += w * k1.y; acc[6]  += w * k1.z; acc[7]  += w * k1.w;
            acc[8]  += w * k2.x; acc[9]  += w * k2.y; acc[10] += w * k2.z; acc[11] += w * k2.w;
            acc[12] += w * k3.x; acc[13] += w * k3.y; acc[14] += w * k3.z; acc[15] += w * k3.w;
        }
        __half hbuf[16];
#pragma unroll
        for (int j = 0; j < 16; ++j) hbuf[j] = __float2half_rn(acc[j]);
        int eo = tid >> 1;            // n
        int e2 = (tid & 1) * 16;      // d0
        uint4* dh = (uint4*)&g_G[br][eo * PITCH + h * 32 + e2];
        dh[0] = ((uint4*)hbuf)[0]; dh[1] = ((uint4*)hbuf)[1];
    }
}

// ---------------------------------------------------------------------------
// out: q = elu(xs@Wq+bq); z in epilogue; out = sum_h z_h*(q_h@G_h)+bo.
// OA: xs -> q.  OB: Wq.  OG: G.  All cp.async.
// ---------------------------------------------------------------------------
#define OA_HI 0
#define OB_HI 34816
#define OG_HI 69632
#define OKS   104448            // ksum 128f
#define OZ    104960            // z 512f
#define OBQ   107008            // bq 128f
#define OBO   107520            // bo 128f
#define SMEM_OUT (OBO + 512)

__global__ __launch_bounds__(512, 1) void out_kernel(
    const float* __restrict__ bq,
    const float* __restrict__ bo, float* __restrict__ out)
{
    extern __shared__ char smem[];
    const u32 sb = smem_u32(smem);
    const int tid = threadIdx.x;
    const int wid = tid >> 5;
    const int lane = tid & 31;
    const int g = lane >> 2, c = lane & 3;
    const size_t row0 = (size_t)blockIdx.x * 128;
    const int br = blockIdx.x >> 4;

    float* ks_s = (float*)(smem + OKS);
    float* zs   = (float*)(smem + OZ);
    float* bq_s = (float*)(smem + OBQ);
    float* bo_s = (float*)(smem + OBO);

    // prefetch xs -> OA, Wq -> OB, G -> OG
    {
        const uint4* xsh = (const uint4*)g_xs[blockIdx.x];
        const uint4* wqh = (const uint4*)g_wt[0];
        const uint4* gh  = (const uint4*)g_G[br];
#pragma unroll
        for (int i = 0; i < 5; ++i) {
            int idx = tid + i * 512;
            if (idx < 2176) {
                cp_async16(sb + OA_HI + idx * 16, xsh + idx);
                cp_async16(sb + OB_HI + idx * 16, wqh + idx);
                cp_async16(sb + OG_HI + idx * 16, gh + idx);
            }
        }
        CP_COMMIT();
    }

    if (tid < 128) ks_s[tid] = g_ksum[(size_t)br * 128 + tid];
    else if (tid < 256) bq_s[tid - 128] = bq[tid - 128];
    else if (tid < 384) bo_s[tid - 256] = bo[tid - 256];

    CP_WAIT0();
    __syncthreads();

    const int arow = (wid & 7) * 16;
    const int ncol0 = (wid >> 3) * 64;
    const u32 aHi = a_base(sb, OA_HI, arow, lane);
    const u32 bHiW = b_base(sb, OB_HI, ncol0, lane);
    const u32 bHiG = b_base(sb, OG_HI, ncol0, lane);

    // q = xs @ Wq
    float qa[8][4];
#pragma unroll
    for (int i = 0; i < 8; ++i)
#pragma unroll
        for (int j = 0; j < 4; ++j) qa[i][j] = 0.f;
    gemm1p_ldsm(aHi, bHiW, qa);

    __syncthreads();   // all xs reads (OA) done

    // epilogue: bias + elu, q into OA, fold z-dot accumulation
    {
        float d00 = 0.f, d01 = 0.f, d10 = 0.f, d11 = 0.f;
#pragma unroll
        for (int nt = 0; nt < 8; ++nt) {
            int col = ncol0 + nt * 8 + 2 * c;
            float2 bb = *(const float2*)(bq_s + col);
            float q0x = elu1(qa[nt][0] + bb.x), q0y = elu1(qa[nt][1] + bb.y);
            float q1x = elu1(qa[nt][2] + bb.x), q1y = elu1(qa[nt][3] + bb.y);
            float2 kk = *(const float2*)(ks_s + col);
            float t0 = q0x * kk.x + q0y * kk.y;
            float t1 = q1x * kk.x + q1y * kk.y;
            if (nt < 4) { d00 += t0; d10 += t1; }
            else        { d01 += t0; d11 += t1; }
            int o0 = ((arow + g) * PITCH + col) * 2;
            int o1 = ((arow + g + 8) * PITCH + col) * 2;
            *(u32*)(smem + OA_HI + o0) = pack_hf2(q0x, q0y);
            *(u32*)(smem + OA_HI + o1) = pack_hf2(q1x, q1y);
        }
        d00 += __shfl_xor_sync(0xffffffffu, d00, 1);
        d00 += __shfl_xor_sync(0xffffffffu, d00, 2);
        d01 += __shfl_xor_sync(0xffffffffu, d01, 1);
        d01 += __shfl_xor_sync(0xffffffffu, d01, 2);
        d10 += __shfl_xor_sync(0xffffffffu, d10, 1);
        d10 += __shfl_xor_sync(0xffffffffu, d10, 2);
        d11 += __shfl_xor_sync(0xffffffffu, d11, 1);
        d11 += __shfl_xor_sync(0xffffffffu, d11, 2);
        if (c == 0) {
            int h0 = ncol0 >> 5;   // 0 or 2
            zs[(arow + g) * 4 + h0]         = d00;
            zs[(arow + g) * 4 + h0 + 1]     = d01;
            zs[(arow + g + 8) * 4 + h0]     = d10;
            zs[(arow + g + 8) * 4 + h0 + 1] = d11;
        }
    }
    __syncthreads();   // q + raw dots visible

    zs[tid] = 1.f / (zs[tid] + 1e-6f);
    __syncthreads();

    // out = sum_h z_h * (q_h @ G_h) + bo
    {
        float acc[8][4];
#pragma unroll
        for (int i = 0; i < 8; ++i)
#pragma unroll
            for (int j = 0; j < 4; ++j) acc[i][j] = 0.f;

#pragma unroll
        for (int h = 0; h < 4; ++h) {
            float pacc[8][4];
#pragma unroll
            for (int i = 0; i < 8; ++i)
#pragma unroll
                for (int j = 0; j < 4; ++j) pacc[i][j] = 0.f;

#pragma unroll
            for (int ks = 0; ks < 2; ++ks) {
                const u32 koff = (u32)((h * 32 + ks * 16) * 2);
                u32 ah[4];
                ldsm_x4(ah, aHi + koff);
#pragma unroll
                for (int np = 0; np < 4; ++np) {
                    u32 bh[4];
                    ldsm_x4(bh, bHiG + koff + (u32)(np * 16 * PITCH * 2));
                    mma16816(pacc[2 * np],     ah, bh[0], bh[1]);
                    mma16816(pacc[2 * np + 1], ah, bh[2], bh[3]);
                }
            }
            float z0 = zs[(arow + g) * 4 + h];
            float z1 = zs[(arow + g + 8) * 4 + h];
#pragma unroll
            for (int nt = 0; nt < 8; ++nt) {
                acc[nt][0] += z0 * pacc[nt][0];
                acc[nt][1] += z0 * pacc[nt][1];
                acc[nt][2] += z1 * pacc[nt][2];
                acc[nt][3] += z1 * pacc[nt][3];
            }
        }

#pragma unroll
        for (int nt = 0; nt < 8; ++nt) {
            int col = ncol0 + nt * 8 + 2 * c;
            float2 bb = *(const float2*)(bo_s + col);
            float2 r0, r1;
            r0.x = acc[nt][0] + bb.x; r0.y = acc[nt][1] + bb.y;
            r1.x = acc[nt][2] + bb.x; r1.y = acc[nt][3] + bb.y;
            size_t ra = row0 + arow + g;
            *(float2*)(out + ra * EDIM + col)       = r0;
            *(float2*)(out + (ra + 8) * EDIM + col) = r1;
        }
    }
}

// ---------------------------------------------------------------------------
extern "C" void kernel_launch(void* const* d_in, const int* in_sizes, int n_in,
                              void* d_out, int out_size)
{
    const float* x  = (const float*)d_in[0];
    const float* Wq = (const float*)d_in[1];
    const float* bq = (const float*)d_in[2];
    const float* Wk = (const float*)d_in[3];
    const float* bk = (const float*)d_in[4];
    const float* Wv = (const float*)d_in[5];
    const float* bv = (const float*)d_in[6];
    const float* Wo = (const float*)d_in[7];
    const float* bo = (const float*)d_in[8];
    float* out = (float*)d_out;

    cudaFuncSetAttribute(kv_kernel, cudaFuncAttributeMaxDynamicSharedMemorySize, SMEM_KV);
    cudaFuncSetAttribute(out_kernel, cudaFuncAttributeMaxDynamicSharedMemorySize, SMEM_OUT);

    wprep_kernel<<<3, 256>>>(Wq, Wk, Wv);
    kv_kernel<<<NCTA, 512, SMEM_KV>>>(x, bk, bv);
    fold_kernel<<<NBR * HEADS, 256>>>(Wo);
    out_kernel<<<NCTA, 512, SMEM_OUT>>>(bq, bo, out);
}

// round 16
// speedup vs baseline: 1.8266x; 1.0368x over previous
#include <cuda_runtime.h>
#include <cuda_fp16.h>
#include <cstdint>

#define BATCH 2
#define RDIM  64
#define CDIM  2048
#define EDIM  128
#define HEADS 4
#define DHEAD 32
#define NROWS (BATCH*RDIM*CDIM)      // 262144
#define NBR   (BATCH*RDIM)           // 128
#define NTILE (NROWS/128)            // 2048 tiles of 128 rows
#define GRID  148                    // persistent CTAs (1/SM)
#define PART_STRIDE 4224

#define PITCH 136                     // fp16 elements per row

typedef unsigned int u32;

// Scratch (device globals)
__device__ float g_ksum[(size_t)NBR * HEADS * DHEAD];
__device__ __align__(16) float g_part[(size_t)NTILE * PART_STRIDE];
__device__ __align__(16) __half g_G[NBR][128 * PITCH];
__device__ __align__(16) __half g_wt[3][128 * PITCH];
__device__ __align__(16) __half g_xs[NTILE][128 * PITCH];

__device__ __forceinline__ float elu1(float x) {
    return x > 0.f ? x + 1.f : expf(x);
}

__device__ __forceinline__ void mma16816(float* d, const u32* a, u32 b0, u32 b1) {
    asm volatile(
        "mma.sync.aligned.m16n8k16.row.col.f32.f16.f16.f32 "
        "{%0,%1,%2,%3}, {%4,%5,%6,%7}, {%8,%9}, {%0,%1,%2,%3};"
        : "+f"(d[0]), "+f"(d[1]), "+f"(d[2]), "+f"(d[3])
        : "r"(a[0]), "r"(a[1]), "r"(a[2]), "r"(a[3]), "r"(b0), "r"(b1));
}

__device__ __forceinline__ void ldsm_x4(u32* r, u32 addr) {
    asm volatile("ldmatrix.sync.aligned.m8n8.x4.shared.b16 {%0,%1,%2,%3}, [%4];"
        : "=r"(r[0]), "=r"(r[1]), "=r"(r[2]), "=r"(r[3]) : "r"(addr));
}

__device__ __forceinline__ void ldsm_x4_t(u32* r, u32 addr) {
    asm volatile("ldmatrix.sync.aligned.m8n8.x4.trans.shared.b16 {%0,%1,%2,%3}, [%4];"
        : "=r"(r[0]), "=r"(r[1]), "=r"(r[2]), "=r"(r[3]) : "r"(addr));
}

__device__ __forceinline__ uint32_t smem_u32(const void* p) {
    uint32_t a;
    asm("{ .reg .u64 t; cvta.to.shared.u64 t, %1; cvt.u32.u64 %0, t; }" : "=r"(a) : "l"(p));
    return a;
}

__device__ __forceinline__ void cp_async16(u32 saddr, const void* gptr) {
    asm volatile("cp.async.cg.shared.global [%0], [%1], 16;"
        :: "r"(saddr), "l"(gptr));
}
#define CP_COMMIT() asm volatile("cp.async.commit_group;" ::: "memory")
#define CP_WAIT0()  asm volatile("cp.async.wait_group 0;" ::: "memory")

__device__ __forceinline__ u32 pack_hf2(float x, float y) {
    __half2 p = __floats2half2_rn(x, y);
    return *(u32*)&p;
}

// single-pass fp16 GEMM, 8 n-tiles, K=128
__device__ __forceinline__ void gemm1p_ldsm(u32 aHi, u32 bHi, float acc[8][4])
{
#pragma unroll
    for (int k0 = 0; k0 < 128; k0 += 16) {
        const u32 koff = (u32)(k0 * 2);
        u32 ah[4];
        ldsm_x4(ah, aHi + koff);
#pragma unroll
        for (int np = 0; np < 4; ++np) {
            u32 bh[4];
            ldsm_x4(bh, bHi + koff + (u32)(np * 16 * PITCH * 2));
            mma16816(acc[2 * np],     ah, bh[0], bh[1]);
            mma16816(acc[2 * np + 1], ah, bh[2], bh[3]);
        }
    }
}

__device__ __forceinline__ u32 a_base(u32 sb, int region, int arow, int lane) {
    return sb + (u32)region +
        (u32)(((arow + (lane & 15)) * PITCH + ((lane & 16) ? 8 : 0)) * 2);
}
__device__ __forceinline__ u32 b_base(u32 sb, int region, int ncol0, int lane) {
    return sb + (u32)region +
        (u32)(((ncol0 + (lane & 7) + ((lane & 16) ? 8 : 0)) * PITCH +
               ((lane & 8) ? 8 : 0)) * 2);
}

// ---------------------------------------------------------------------------
// wprep: W[k][n] fp32 -> Wt[n][k] fp16. grid=3.
// ---------------------------------------------------------------------------
__global__ __launch_bounds__(256) void wprep_kernel(
    const float* __restrict__ Wq, const float* __restrict__ Wk,
    const float* __restrict__ Wv)
{
    const float* Wl[3] = {Wq, Wk, Wv};
    const float* W = Wl[blockIdx.x];
    __half* hi = g_wt[blockIdx.x];
    for (int i = threadIdx.x; i < 128 * 128; i += 256) {
        int k = i >> 7, n = i & 127;
        hi[n * PITCH + k] = __float2half_rn(W[i]);
    }
}

// ---------------------------------------------------------------------------
// KV persistent: 148 CTAs, ~14 tiles each. W resident; per tile:
// x convert/export -> k gemm -> k epi -> v gemm -> v epi -> KtV partials.
// ---------------------------------------------------------------------------
#define WK_R  0
#define WV_R  34816
#define XA_R  69632
#define KK_R  104448
#define VV_R  139264
#define KBIAS 174080            // 2*128 f
#define KKSUM 175104            // float[8][128]
#define SMEM_KV (KKSUM + 4096)  // 179200

__global__ __launch_bounds__(512, 1) void kv_kernel(
    const float* __restrict__ x,
    const float* __restrict__ bk, const float* __restrict__ bv)
{
    extern __shared__ char smem[];
    const u32 sb = smem_u32(smem);
    const int tid = threadIdx.x;
    const int wid = tid >> 5;
    const int lane = tid & 31;
    const int g = lane >> 2, c = lane & 3;

    float* sbias = (float*)(smem + KBIAS);
    float* sksum = (float*)(smem + KKSUM);
    if (tid < 128) {
        sbias[tid]       = bk[tid];
        sbias[128 + tid] = bv[tid];
    }

    // prefetch Wk, Wv ONCE
    {
        const uint4* wkh = (const uint4*)g_wt[1];
        const uint4* wvh = (const uint4*)g_wt[2];
#pragma unroll
        for (int i = 0; i < 5; ++i) {
            int idx = tid + i * 512;
            if (idx < 2176) {
                cp_async16(sb + WK_R + idx * 16, wkh + idx);
                cp_async16(sb + WV_R + idx * 16, wvh + idx);
            }
        }
        CP_COMMIT();
    }

    const int ts = (int)(((long long)blockIdx.x * NTILE) / GRID);
    const int te = (int)(((long long)(blockIdx.x + 1) * NTILE) / GRID);

    const int arow = (wid & 7) * 16;
    const int ncol0 = (wid >> 3) * 64;
    const int aw = wid & 7;

    const u32 aHi  = a_base(sb, XA_R, arow, lane);
    const u32 bWK  = b_base(sb, WK_R, ncol0, lane);
    const u32 bWV  = b_base(sb, WV_R, ncol0, lane);

    // KtV-phase lane bases (fixed regions)
    const int kh  = wid & 3;
    const int mt  = (wid >> 2) & 1;
    const int np  = wid >> 3;
    const u32 a_roff = (u32)(((lane & 7) + ((lane & 16) ? 8 : 0)) * (PITCH * 2));
    const u32 a_coff = (u32)((kh * 32 + mt * 16 + ((lane & 8) ? 8 : 0)) * 2);
    const u32 b_roff = (u32)(((lane & 7) + ((lane & 8) ? 8 : 0)) * (PITCH * 2));
    const u32 b_coff = (u32)((kh * 32 + np * 16 + ((lane & 16) ? 8 : 0)) * 2);
    const u32 ktv_a = sb + KK_R + a_roff + a_coff;
    const u32 ktv_b = sb + VV_R + b_roff + b_coff;

    bool first = true;
    for (int t = ts; t < te; ++t) {
        const size_t row0 = (size_t)t * 128;

        // x convert into XA + export to g_xs
        {
            const float4* xg = reinterpret_cast<const float4*>(x + row0 * EDIM);
            char* xs_hi = (char*)g_xs[t];
#pragma unroll
            for (int i = 0; i < 8; ++i) {
                int idx = tid + i * 512;
                int row = idx >> 5;
                int c4  = (idx & 31) << 2;
                float4 v = xg[idx];
                uint2 hh = make_uint2(pack_hf2(v.x, v.y), pack_hf2(v.z, v.w));
                int off = (row * PITCH + c4) * 2;
                *(uint2*)(smem + XA_R + off) = hh;
                *(uint2*)(xs_hi + off) = hh;
            }
        }
        if (first) { CP_WAIT0(); first = false; }
        __syncthreads();   // XA ready; prev tile's KK/VV consumers done

        // ---- k projection ----
        {
            float acc[8][4];
#pragma unroll
            for (int i = 0; i < 8; ++i)
#pragma unroll
                for (int j = 0; j < 4; ++j) acc[i][j] = 0.f;
            gemm1p_ldsm(aHi, bWK, acc);

#pragma unroll
            for (int nt = 0; nt < 8; ++nt) {
                int col = ncol0 + nt * 8 + 2 * c;
                float2 bb = *(const float2*)(sbias + col);
                float k0x = elu1(acc[nt][0] + bb.x), k0y = elu1(acc[nt][1] + bb.y);
                float k1x = elu1(acc[nt][2] + bb.x), k1y = elu1(acc[nt][3] + bb.y);
                int o0 = ((arow + g) * PITCH + col) * 2;
                int o1 = ((arow + g + 8) * PITCH + col) * 2;
                *(u32*)(smem + KK_R + o0) = pack_hf2(k0x, k0y);
                *(u32*)(smem + KK_R + o1) = pack_hf2(k1x, k1y);
                float s0 = k0x + k1x;
                float s1 = k0y + k1y;
                s0 += __shfl_xor_sync(0xffffffffu, s0, 16);
                s0 += __shfl_xor_sync(0xffffffffu, s0, 8);
                s0 += __shfl_xor_sync(0xffffffffu, s0, 4);
                s1 += __shfl_xor_sync(0xffffffffu, s1, 16);
                s1 += __shfl_xor_sync(0xffffffffu, s1, 8);
                s1 += __shfl_xor_sync(0xffffffffu, s1, 4);
                if (lane < 4) {
                    sksum[aw * 128 + col]     = s0;
                    sksum[aw * 128 + col + 1] = s1;
                }
            }
        }

        // ---- v projection ----
        {
            float acc[8][4];
#pragma unroll
            for (int i = 0; i < 8; ++i)
#pragma unroll
                for (int j = 0; j < 4; ++j) acc[i][j] = 0.f;
            gemm1p_ldsm(aHi, bWV, acc);

            const float* bias = sbias + 128;
#pragma unroll
            for (int nt = 0; nt < 8; ++nt) {
                int col = ncol0 + nt * 8 + 2 * c;
                float2 bb = *(const float2*)(bias + col);
                int o0 = ((arow + g) * PITCH + col) * 2;
                int o1 = ((arow + g + 8) * PITCH + col) * 2;
                *(u32*)(smem + VV_R + o0) = pack_hf2(acc[nt][0] + bb.x, acc[nt][1] + bb.y);
                *(u32*)(smem + VV_R + o1) = pack_hf2(acc[nt][2] + bb.x, acc[nt][3] + bb.y);
            }
        }
        __syncthreads();   // k + v + sksum complete

        if (tid < 128) {
            float s = 0.f;
#pragma unroll
            for (int i = 0; i < 8; ++i) s += sksum[i * 128 + tid];
            g_part[(size_t)t * PART_STRIDE + 4096 + tid] = s;
        }

        // ---- KtV partials ----
        {
            float acc[2][4];
#pragma unroll
            for (int i = 0; i < 2; ++i)
#pragma unroll
                for (int j = 0; j < 4; ++j) acc[i][j] = 0.f;

#pragma unroll
            for (int c0 = 0; c0 < 128; c0 += 16) {
                u32 off = (u32)(c0 * (PITCH * 2));
                u32 ah[4], bh[4];
                ldsm_x4_t(ah, ktv_a + off);
                ldsm_x4_t(bh, ktv_b + off);
                mma16816(acc[0], ah, bh[0], bh[1]);
                mma16816(acc[1], ah, bh[2], bh[3]);
            }

            float* dst = g_part + (size_t)t * PART_STRIDE + kh * 1024;
#pragma unroll
            for (int nt = 0; nt < 2; ++nt) {
                int d_lo = mt * 16 + g;
                int e_lo = np * 16 + nt * 8 + 2 * c;
                *(float2*)&dst[d_lo * 32 + e_lo]       = make_float2(acc[nt][0], acc[nt][1]);
                *(float2*)&dst[(d_lo + 8) * 32 + e_lo] = make_float2(acc[nt][2], acc[nt][3]);
            }
        }
    }
}

// ---------------------------------------------------------------------------
// fold: reduce 16 partials -> KtV; ksum (h==0); G -> fp16 [n][k].
// ---------------------------------------------------------------------------
__global__ __launch_bounds__(256) void fold_kernel(const float* __restrict__ Wo)
{
    __shared__ float ktv_s[1024];
    __shared__ float ws[4096];

    const int tid = threadIdx.x;
    const int br  = blockIdx.x >> 2;
    const int h   = blockIdx.x & 3;
    const float* base = g_part + (size_t)br * 16 * PART_STRIDE;

    {
        float v0 = 0.f, v1 = 0.f, v2 = 0.f, v3 = 0.f;
#pragma unroll 4
        for (int i = 0; i < 16; ++i) {
            float4 p = *(const float4*)(base + (size_t)i * PART_STRIDE + h * 1024 + tid * 4);
            v0 += p.x; v1 += p.y; v2 += p.z; v3 += p.w;
        }
        int d = tid >> 3, e0 = (tid & 7) * 4;
        ktv_s[(e0 + 0) * 32 + d] = v0;
        ktv_s[(e0 + 1) * 32 + d] = v1;
        ktv_s[(e0 + 2) * 32 + d] = v2;
        ktv_s[(e0 + 3) * 32 + d] = v3;
    }

    if (h == 0 && tid < 128) {
        float s = 0.f;
#pragma unroll 4
        for (int i = 0; i < 16; ++i)
            s += base[(size_t)i * PART_STRIDE + 4096 + tid];
        g_ksum[(size_t)br * 128 + tid] = s;
    }

    {
        const float4* wg = reinterpret_cast<const float4*>(Wo + h * 4096);
#pragma unroll
        for (int i = 0; i < 4; ++i)
            reinterpret_cast<float4*>(ws)[tid + i * 256] = wg[tid + i * 256];
    }
    __syncthreads();

    {
        const int n  = tid >> 1;
        const int d0 = (tid & 1) * 16;
        float acc[16];
#pragma unroll
        for (int j = 0; j < 16; ++j) acc[j] = 0.f;
#pragma unroll 4
        for (int dp = 0; dp < 32; ++dp) {
            float w = ws[dp * 128 + n];
            const float4* kp = (const float4*)(ktv_s + dp * 32 + d0);
            float4 k0 = kp[0], k1 = kp[1], k2 = kp[2], k3 = kp[3];
            acc[0]  += w * k0.x; acc[1]  += w * k0.y; acc[2]  += w * k0.z; acc[3]  += w * k0.w;
            acc[4]  += w * k1.x; acc[5]  += w * k1.y; acc[6]  += w * k1.z; acc[7]  += w * k1.w;
            acc[8]  += w * k2.x; acc[9]  += w * k2.y; acc[10] += w * k2.z; acc[11] += w * k2.w;
            acc[12] += w * k3.x; acc[13] += w * k3.y; acc[14] += w * k3.z; acc[15] += w * k3.w;
        }
        __half hbuf[16];
#pragma unroll
        for (int j = 0; j < 16; ++j) hbuf[j] = __float2half_rn(acc[j]);
        uint4* dh = (uint4*)&g_G[br][n * PITCH + h * 32 + d0];
        dh[0] = ((uint4*)hbuf)[0]; dh[1] = ((uint4*)hbuf)[1];
    }
}

// ---------------------------------------------------------------------------
// out persistent: 148 CTAs. Wq resident; G per br; xs double-buffered cp.async.
// per tile: q gemm -> SYNC -> epilogue(z-dots) -> G gemm (inline z) -> store.
// ---------------------------------------------------------------------------
#define XA0_R 0
#define XA1_R 34816
#define WQ_R  69632
#define OG_R  104448
#define OKS   139264            // ksum 128f
#define OZ    139776            // raw dots 512f
#define OBQ   141824            // bq 128f
#define OBO   142336            // bo 128f
#define SMEM_OUT (OBO + 512)

__global__ __launch_bounds__(512, 1) void out_kernel(
    const float* __restrict__ bq,
    const float* __restrict__ bo, float* __restrict__ out)
{
    extern __shared__ char smem[];
    const u32 sb = smem_u32(smem);
    const int tid = threadIdx.x;
    const int wid = tid >> 5;
    const int lane = tid & 31;
    const int g = lane >> 2, c = lane & 3;

    float* ks_s = (float*)(smem + OKS);
    float* zs   = (float*)(smem + OZ);
    float* bq_s = (float*)(smem + OBQ);
    float* bo_s = (float*)(smem + OBO);

    const int ts = (int)(((long long)blockIdx.x * NTILE) / GRID);
    const int te = (int)(((long long)(blockIdx.x + 1) * NTILE) / GRID);
    int br = ts >> 4;

    // prologue: Wq (once), G(br), xs(ts)
    {
        const uint4* wqh = (const uint4*)g_wt[0];
        const uint4* gh  = (const uint4*)g_G[br];
        const uint4* xsh = (const uint4*)g_xs[ts];
#pragma unroll
        for (int i = 0; i < 5; ++i) {
            int idx = tid + i * 512;
            if (idx < 2176) {
                cp_async16(sb + WQ_R + idx * 16, wqh + idx);
                cp_async16(sb + OG_R + idx * 16, gh + idx);
                cp_async16(sb + XA0_R + idx * 16, xsh + idx);
            }
        }
        CP_COMMIT();
    }
    if (tid < 128) ks_s[tid] = g_ksum[(size_t)br * 128 + tid];
    else if (tid < 256) bq_s[tid - 128] = bq[tid - 128];
    else if (tid < 384) bo_s[tid - 256] = bo[tid - 256];

    const int arow = (wid & 7) * 16;
    const int ncol0 = (wid >> 3) * 64;
    const u32 bWQ = b_base(sb, WQ_R, ncol0, lane);
    const u32 bOG = b_base(sb, OG_R, ncol0, lane);

    int buf = 0;
    for (int t = ts; t < te; ++t) {
        CP_WAIT0();
        __syncthreads();   // xs[t] (+G/ks on br change) ready; prev-tile consumers done

        // stream next tile's xs into the other buffer
        if (t + 1 < te) {
            const uint4* xsn = (const uint4*)g_xs[t + 1];
            const u32 dstR = (u32)(buf ? XA0_R : XA1_R);
#pragma unroll
            for (int i = 0; i < 5; ++i) {
                int idx = tid + i * 512;
                if (idx < 2176) cp_async16(sb + dstR + idx * 16, xsn + idx);
            }
            CP_COMMIT();
        }

        const int xaR = buf ? XA1_R : XA0_R;
        const u32 aHi = a_base(sb, xaR, arow, lane);

        // q = xs @ Wq
        float qa[8][4];
#pragma unroll
        for (int i = 0; i < 8; ++i)
#pragma unroll
            for (int j = 0; j < 4; ++j) qa[i][j] = 0.f;
        gemm1p_ldsm(aHi, bWQ, qa);

        __syncthreads();   // ALL warps' xs reads done before q overwrites XA (WAR fix)

        // epilogue: bias + elu, q into XA[buf], raw z-dots
        {
            float d00 = 0.f, d01 = 0.f, d10 = 0.f, d11 = 0.f;
#pragma unroll
            for (int nt = 0; nt < 8; ++nt) {
                int col = ncol0 + nt * 8 + 2 * c;
                float2 bb = *(const float2*)(bq_s + col);
                float q0x = elu1(qa[nt][0] + bb.x), q0y = elu1(qa[nt][1] + bb.y);
                float q1x = elu1(qa[nt][2] + bb.x), q1y = elu1(qa[nt][3] + bb.y);
                float2 kk = *(const float2*)(ks_s + col);
                float t0 = q0x * kk.x + q0y * kk.y;
                float t1 = q1x * kk.x + q1y * kk.y;
                if (nt < 4) { d00 += t0; d10 += t1; }
                else        { d01 += t0; d11 += t1; }
                int o0 = ((arow + g) * PITCH + col) * 2;
                int o1 = ((arow + g + 8) * PITCH + col) * 2;
                *(u32*)(smem + xaR + o0) = pack_hf2(q0x, q0y);
                *(u32*)(smem + xaR + o1) = pack_hf2(q1x, q1y);
            }
            d00 += __shfl_xor_sync(0xffffffffu, d00, 1);
            d00 += __shfl_xor_sync(0xffffffffu, d00, 2);
            d01 += __shfl_xor_sync(0xffffffffu, d01, 1);
            d01 += __shfl_xor_sync(0xffffffffu, d01, 2);
            d10 += __shfl_xor_sync(0xffffffffu, d10, 1);
            d10 += __shfl_xor_sync(0xffffffffu, d10, 2);
            d11 += __shfl_xor_sync(0xffffffffu, d11, 1);
            d11 += __shfl_xor_sync(0xffffffffu, d11, 2);
            if (c == 0) {
                int h0 = ncol0 >> 5;
                zs[(arow + g) * 4 + h0]         = d00;
                zs[(arow + g) * 4 + h0 + 1]     = d01;
                zs[(arow + g + 8) * 4 + h0]     = d10;
                zs[(arow + g + 8) * 4 + h0 + 1] = d11;
            }
        }
        __syncthreads();   // q + raw dots visible cross-warp

        // out = sum_h z_h * (q_h @ G_h) + bo  (z inlined)
        {
            const size_t row0 = (size_t)t * 128;
            float acc[8][4];
#pragma unroll
            for (int i = 0; i < 8; ++i)
#pragma unroll
                for (int j = 0; j < 4; ++j) acc[i][j] = 0.f;

#pragma unroll
            for (int h = 0; h < 4; ++h) {
                float pacc[8][4];
#pragma unroll
                for (int i = 0; i < 8; ++i)
#pragma unroll
                    for (int j = 0; j < 4; ++j) pacc[i][j] = 0.f;

#pragma unroll
                for (int ks = 0; ks < 2; ++ks) {
                    const u32 koff = (u32)((h * 32 + ks * 16) * 2);
                    u32 ah[4];
                    ldsm_x4(ah, aHi + koff);
#pragma unroll
                    for (int np = 0; np < 4; ++np) {
                        u32 bh[4];
                        ldsm_x4(bh, bOG + koff + (u32)(np * 16 * PITCH * 2));
                        mma16816(pacc[2 * np],     ah, bh[0], bh[1]);
                        mma16816(pacc[2 * np + 1], ah, bh[2], bh[3]);
                    }
                }
                float z0 = 1.f / (zs[(arow + g) * 4 + h] + 1e-6f);
                float z1 = 1.f / (zs[(arow + g + 8) * 4 + h] + 1e-6f);
#pragma unroll
                for (int nt = 0; nt < 8; ++nt) {
                    acc[nt][0] += z0 * pacc[nt][0];
                    acc[nt][1] += z0 * pacc[nt][1];
                    acc[nt][2] += z1 * pacc[nt][2];
                    acc[nt][3] += z1 * pacc[nt][3];
                }
            }

#pragma unroll
            for (int nt = 0; nt < 8; ++nt) {
                int col = ncol0 + nt * 8 + 2 * c;
                float2 bb = *(const float2*)(bo_s + col);
                float2 r0, r1;
                r0.x = acc[nt][0] + bb.x; r0.y = acc[nt][1] + bb.y;
                r1.x = acc[nt][2] + bb.x; r1.y = acc[nt][3] + bb.y;
                size_t ra = row0 + arow + g;
                *(float2*)(out + ra * EDIM + col)       = r0;
                *(float2*)(out + (ra + 8) * EDIM + col) = r1;
            }
        }

        // br change for next tile? reload G + ksum (once per 16 tiles)
        if (t + 1 < te) {
            int nbr = (t + 1) >> 4;
            if (nbr != br) {
                __syncthreads();   // all G reads done
                br = nbr;
                const uint4* gh = (const uint4*)g_G[br];
#pragma unroll
                for (int i = 0; i < 5; ++i) {
                    int idx = tid + i * 512;
                    if (idx < 2176) cp_async16(sb + OG_R + idx * 16, gh + idx);
                }
                CP_COMMIT();
                if (tid < 128) ks_s[tid] = g_ksum[(size_t)br * 128 + tid];
            }
        }
        buf ^= 1;
    }
}

// ---------------------------------------------------------------------------
extern "C" void kernel_launch(void* const* d_in, const int* in_sizes, int n_in,
                              void* d_out, int out_size)
{
    const float* x  = (const float*)d_in[0];
    const float* Wq = (const float*)d_in[1];
    const float* bq = (const float*)d_in[2];
    const float* Wk = (const float*)d_in[3];
    const float* bk = (const float*)d_in[4];
    const float* Wv = (const float*)d_in[5];
    const float* bv = (const float*)d_in[6];
    const float* Wo = (const float*)d_in[7];
    const float* bo = (const float*)d_in[8];
    float* out = (float*)d_out;

    cudaFuncSetAttribute(kv_kernel, cudaFuncAttributeMaxDynamicSharedMemorySize, SMEM_KV);
    cudaFuncSetAttribute(out_kernel, cudaFuncAttributeMaxDynamicSharedMemorySize, SMEM_OUT);

    wprep_kernel<<<3, 256>>>(Wq, Wk, Wv);
    kv_kernel<<<GRID, 512, SMEM_KV>>>(x, bk, bv);
    fold_kernel<<<NBR * HEADS, 256>>>(Wo);
    out_kernel<<<GRID, 512, SMEM_OUT>>>(bq, bo, out);
}